// round 1
// baseline (speedup 1.0000x reference)
#include <cuda_runtime.h>
#include <math.h>
#include <stdint.h>

// Problem constants
#define BB   2
#define TT   2048
#define DD   1024
#define HH   16
#define DQK  64
#define HDIM 4096
#define VV   32000
#define LL   4
#define MM   (BB*TT)   // 4096 rows

// ---------------------------------------------------------------------------
// Static device scratch (no allocations allowed)
// ---------------------------------------------------------------------------
__device__ float g_x [MM*DD];
__device__ float g_xn[MM*DD];
__device__ float g_q [MM*DD];
__device__ float g_k [MM*DD];
__device__ float g_v [MM*DD];
__device__ float g_y [MM*DD];
__device__ float g_h [MM*HDIM];

// ---------------------------------------------------------------------------
// Embedding + positional encoding
// x[b,t,d] = emb[shifted_tok][d] + sin(t / LEN_MAX^((d-k)/D) + (pi/2)*k), k=d&1
// ---------------------------------------------------------------------------
__global__ void embed_kernel(const int* __restrict__ tokens,
                             const float* __restrict__ emb,
                             float* __restrict__ x)
{
    int idx = blockIdx.x * blockDim.x + threadIdx.x;
    if (idx >= MM * DD) return;
    int d  = idx & (DD - 1);
    int mt = idx >> 10;            // row index b*T + t
    int b  = mt >> 11;
    int t  = mt & (TT - 1);
    int tok = (t == 0) ? 0 : tokens[b * TT + t - 1];
    int k = d & 1;
    double e = (double)(d - k) / (double)DD;
    float freq = (float)exp(-e * 11.512925464970229);   // LEN_MAX^-e, LEN_MAX=1e5
    float arg = (float)t * freq + 1.5707963267948966f * (float)k;
    x[idx] = emb[(size_t)tok * DD + d] + sinf(arg);
}

// ---------------------------------------------------------------------------
// LayerNorm: one block per row of 1024, 256 threads, two-pass (mean then var)
// ---------------------------------------------------------------------------
__global__ __launch_bounds__(256) void ln_kernel(const float* __restrict__ x,
                                                 float* __restrict__ y,
                                                 const float* __restrict__ w,
                                                 const float* __restrict__ b)
{
    __shared__ float red[8];
    int row = blockIdx.x;
    int tid = threadIdx.x;
    const float* xr = x + (size_t)row * DD;
    float4 xv = *(const float4*)&xr[tid * 4];

    float s = xv.x + xv.y + xv.z + xv.w;
    #pragma unroll
    for (int o = 16; o > 0; o >>= 1) s += __shfl_xor_sync(0xffffffffu, s, o);
    if ((tid & 31) == 0) red[tid >> 5] = s;
    __syncthreads();
    float tot = 0.f;
    #pragma unroll
    for (int i = 0; i < 8; i++) tot += red[i];
    float mean = tot * (1.0f / DD);
    __syncthreads();

    float dx0 = xv.x - mean, dx1 = xv.y - mean, dx2 = xv.z - mean, dx3 = xv.w - mean;
    float s2 = dx0*dx0 + dx1*dx1 + dx2*dx2 + dx3*dx3;
    #pragma unroll
    for (int o = 16; o > 0; o >>= 1) s2 += __shfl_xor_sync(0xffffffffu, s2, o);
    if ((tid & 31) == 0) red[tid >> 5] = s2;
    __syncthreads();
    float tot2 = 0.f;
    #pragma unroll
    for (int i = 0; i < 8; i++) tot2 += red[i];
    float inv = rsqrtf(tot2 * (1.0f / DD) + 1e-5f);

    int c = tid * 4;
    float4 wv = *(const float4*)&w[c];
    float4 bv = *(const float4*)&b[c];
    float4 ov;
    ov.x = dx0 * inv * wv.x + bv.x;
    ov.y = dx1 * inv * wv.y + bv.y;
    ov.z = dx2 * inv * wv.z + bv.z;
    ov.w = dx3 * inv * wv.w + bv.w;
    *(float4*)&(y + (size_t)row * DD)[c] = ov;
}

// ---------------------------------------------------------------------------
// SGEMM: C[M,N] (+)= A[M,K] * op(B) (+ bias) (relu)
//   TRANSB=1: B stored [N,K] row-major (torch Linear weight) -> C = A * B^T
//   TRANSB=0: B stored [K,N] row-major                         -> C = A * B
// Tiles: 128x128x8, 256 threads, 8x8 per thread.
// Requires M%128==0, N%128==0, K%8==0 (holds for all calls here).
// ---------------------------------------------------------------------------
template<bool TRANSB, bool BIAS, bool RELU, bool ACCUM>
__global__ __launch_bounds__(256) void sgemm(const float* __restrict__ A,
                                             const float* __restrict__ Bm,
                                             const float* __restrict__ bias,
                                             float* __restrict__ C,
                                             int Mdim, int Ndim, int Kdim)
{
    __shared__ float As[8][128];
    __shared__ float Bs[8][128];

    const int tid  = threadIdx.x;
    const int tx   = tid & 15;
    const int ty   = tid >> 4;
    const int row0 = blockIdx.y * 128;
    const int col0 = blockIdx.x * 128;

    float acc[8][8];
    #pragma unroll
    for (int i = 0; i < 8; i++)
        #pragma unroll
        for (int j = 0; j < 8; j++) acc[i][j] = 0.f;

    const int arow = tid >> 1, acol = (tid & 1) * 4;

    for (int k0 = 0; k0 < Kdim; k0 += 8) {
        // load A tile (transposed into smem)
        float4 av = *(const float4*)&A[(size_t)(row0 + arow) * Kdim + k0 + acol];
        As[acol + 0][arow] = av.x;
        As[acol + 1][arow] = av.y;
        As[acol + 2][arow] = av.z;
        As[acol + 3][arow] = av.w;
        // load B tile
        if (TRANSB) {
            int bn = tid >> 1, bk = (tid & 1) * 4;
            float4 bv = *(const float4*)&Bm[(size_t)(col0 + bn) * Kdim + k0 + bk];
            Bs[bk + 0][bn] = bv.x;
            Bs[bk + 1][bn] = bv.y;
            Bs[bk + 2][bn] = bv.z;
            Bs[bk + 3][bn] = bv.w;
        } else {
            int bk = tid >> 5, bn = (tid & 31) * 4;
            float4 bv = *(const float4*)&Bm[(size_t)(k0 + bk) * Ndim + col0 + bn];
            *(float4*)&Bs[bk][bn] = bv;
        }
        __syncthreads();

        #pragma unroll
        for (int k = 0; k < 8; k++) {
            float a[8], bfr[8];
            *(float4*)&a[0]   = *(const float4*)&As[k][ty * 8];
            *(float4*)&a[4]   = *(const float4*)&As[k][ty * 8 + 4];
            *(float4*)&bfr[0] = *(const float4*)&Bs[k][tx * 8];
            *(float4*)&bfr[4] = *(const float4*)&Bs[k][tx * 8 + 4];
            #pragma unroll
            for (int i = 0; i < 8; i++)
                #pragma unroll
                for (int j = 0; j < 8; j++)
                    acc[i][j] += a[i] * bfr[j];
        }
        __syncthreads();
    }

    #pragma unroll
    for (int i = 0; i < 8; i++) {
        size_t r = (size_t)(row0 + ty * 8 + i);
        #pragma unroll
        for (int j = 0; j < 8; j += 4) {
            int c = col0 + tx * 8 + j;
            float4 v = make_float4(acc[i][j], acc[i][j+1], acc[i][j+2], acc[i][j+3]);
            if (BIAS) {
                float4 bb = *(const float4*)&bias[c];
                v.x += bb.x; v.y += bb.y; v.z += bb.z; v.w += bb.w;
            }
            if (RELU) {
                v.x = fmaxf(v.x, 0.f); v.y = fmaxf(v.y, 0.f);
                v.z = fmaxf(v.z, 0.f); v.w = fmaxf(v.w, 0.f);
            }
            if (ACCUM) {
                float4 o = *(const float4*)&C[r * Ndim + c];
                v.x += o.x; v.y += o.y; v.z += o.z; v.w += o.w;
            }
            *(float4*)&C[r * Ndim + c] = v;
        }
    }
}

// ---------------------------------------------------------------------------
// Causal attention, fp32, flash-style online softmax.
// Q,K,V,Y layout: [B, T, H*64] (head h at column offset h*64).
// Block: 64 threads = 64 queries (one query/thread).
// grid.x = T/64 (query tile), grid.y = B*H.
// ---------------------------------------------------------------------------
__global__ __launch_bounds__(64) void attn_kernel(const float* __restrict__ Q,
                                                  const float* __restrict__ K,
                                                  const float* __restrict__ V,
                                                  float* __restrict__ Y)
{
    __shared__ float Ks[64][64];   // K tile, then reused for V tile
    __shared__ float S[64][65];    // per-thread score row (padded)

    const int bh = blockIdx.y;
    const int b  = bh / HH;
    const int h  = bh % HH;
    const int qt = blockIdx.x;
    const int tid = threadIdx.x;
    const int t = qt * 64 + tid;               // global query index
    const float scale = 0.125f;                // 1/sqrt(64)

    // load this thread's query row into registers
    float q[64];
    const float* qp = Q + (size_t)(b * TT + t) * DD + h * 64;
    #pragma unroll
    for (int i = 0; i < 64; i += 4) {
        float4 v4 = *(const float4*)&qp[i];
        q[i] = v4.x; q[i+1] = v4.y; q[i+2] = v4.z; q[i+3] = v4.w;
    }

    float m = -1e30f, l = 0.f;
    float acc[64];
    #pragma unroll
    for (int i = 0; i < 64; i++) acc[i] = 0.f;

    for (int s0 = 0; s0 <= qt * 64; s0 += 64) {
        __syncthreads();   // previous tile's V reads complete before overwrite
        // cooperative load of K tile [64 keys x 64 dims]
        #pragma unroll
        for (int it = 0; it < 16; it++) {
            int f = it * 64 + tid;        // float4 index in tile
            int r = f >> 4, c4 = (f & 15) << 2;
            *(float4*)&Ks[r][c4] =
                *(const float4*)&K[(size_t)(b * TT + s0 + r) * DD + h * 64 + c4];
        }
        __syncthreads();

        // scores + running max
        float mx = -1e30f;
        for (int s = 0; s < 64; s++) {
            float d0 = 0.f, d1 = 0.f, d2 = 0.f, d3 = 0.f;
            #pragma unroll
            for (int i = 0; i < 64; i += 16) {
                float4 k0 = *(const float4*)&Ks[s][i];
                float4 k1 = *(const float4*)&Ks[s][i + 4];
                float4 k2 = *(const float4*)&Ks[s][i + 8];
                float4 k3 = *(const float4*)&Ks[s][i + 12];
                d0 += q[i+0]*k0.x + q[i+1]*k0.y + q[i+2]*k0.z + q[i+3]*k0.w;
                d1 += q[i+4]*k1.x + q[i+5]*k1.y + q[i+6]*k1.z + q[i+7]*k1.w;
                d2 += q[i+8]*k2.x + q[i+9]*k2.y + q[i+10]*k2.z + q[i+11]*k2.w;
                d3 += q[i+12]*k3.x + q[i+13]*k3.y + q[i+14]*k3.z + q[i+15]*k3.w;
            }
            float dsc = ((d0 + d1) + (d2 + d3)) * scale;
            if (s0 + s > t) dsc = -1e30f;     // causal mask
            S[tid][s] = dsc;
            mx = fmaxf(mx, dsc);
        }

        // online softmax update
        float mnew = fmaxf(m, mx);
        float corr = __expf(m - mnew);
        l *= corr;
        #pragma unroll
        for (int i = 0; i < 64; i++) acc[i] *= corr;
        float lsum = 0.f;
        for (int s = 0; s < 64; s++) {
            float p = __expf(S[tid][s] - mnew);
            S[tid][s] = p;
            lsum += p;
        }
        l += lsum;
        m = mnew;

        __syncthreads();   // all score reads of Ks done
        // load V tile into Ks
        #pragma unroll
        for (int it = 0; it < 16; it++) {
            int f = it * 64 + tid;
            int r = f >> 4, c4 = (f & 15) << 2;
            *(float4*)&Ks[r][c4] =
                *(const float4*)&V[(size_t)(b * TT + s0 + r) * DD + h * 64 + c4];
        }
        __syncthreads();

        // accumulate P*V
        for (int s = 0; s < 64; s++) {
            float p = S[tid][s];
            #pragma unroll
            for (int i = 0; i < 64; i += 4) {
                float4 vv = *(const float4*)&Ks[s][i];
                acc[i+0] += p * vv.x;
                acc[i+1] += p * vv.y;
                acc[i+2] += p * vv.z;
                acc[i+3] += p * vv.w;
            }
        }
    }

    float inv = 1.0f / l;
    float* yp = Y + (size_t)(b * TT + t) * DD + h * 64;
    #pragma unroll
    for (int i = 0; i < 64; i += 4) {
        float4 o = make_float4(acc[i]*inv, acc[i+1]*inv, acc[i+2]*inv, acc[i+3]*inv);
        *(float4*)&yp[i] = o;
    }
}

// ---------------------------------------------------------------------------
// Launch
// ---------------------------------------------------------------------------
extern "C" void kernel_launch(void* const* d_in, const int* in_sizes, int n_in,
                              void* d_out, int out_size)
{
    const int*   tokens = (const int*)  d_in[0];
    const float* emb    = (const float*)d_in[1];
    const float* ln1_w  = (const float*)d_in[2];
    const float* ln1_b  = (const float*)d_in[3];
    const float* w_q    = (const float*)d_in[4];
    const float* w_k    = (const float*)d_in[5];
    const float* w_v    = (const float*)d_in[6];
    const float* w_o    = (const float*)d_in[7];
    const float* ln2_w  = (const float*)d_in[8];
    const float* ln2_b  = (const float*)d_in[9];
    const float* w1     = (const float*)d_in[10];
    const float* b1     = (const float*)d_in[11];
    const float* w2     = (const float*)d_in[12];
    const float* b2     = (const float*)d_in[13];
    const float* ro_w   = (const float*)d_in[14];
    const float* ro_b   = (const float*)d_in[15];
    float* out = (float*)d_out;

    float *x, *xn, *q, *k, *v, *y, *h;
    cudaGetSymbolAddress((void**)&x,  g_x);
    cudaGetSymbolAddress((void**)&xn, g_xn);
    cudaGetSymbolAddress((void**)&q,  g_q);
    cudaGetSymbolAddress((void**)&k,  g_k);
    cudaGetSymbolAddress((void**)&v,  g_v);
    cudaGetSymbolAddress((void**)&y,  g_y);
    cudaGetSymbolAddress((void**)&h,  g_h);

    embed_kernel<<<(MM * DD + 255) / 256, 256>>>(tokens, emb, x);

    const dim3 gD(DD / 128, MM / 128);       // N=1024 GEMMs
    const dim3 gH(HDIM / 128, MM / 128);     // N=4096 GEMM
    const dim3 gV(VV / 128, MM / 128);       // N=32000 GEMM
    const dim3 gA(TT / 64, BB * HH);         // attention

    for (int l = 0; l < LL; l++) {
        size_t wqkv_off = (size_t)l * HH * DQK * DD;   // = l * 1024*1024
        size_t wo_off   = (size_t)l * DD * DD;
        size_t w1_off   = (size_t)l * HDIM * DD;
        size_t w2_off   = (size_t)l * DD * HDIM;

        ln_kernel<<<MM, 256>>>(x, xn, ln1_w + (size_t)l * DD, ln1_b + (size_t)l * DD);

        sgemm<true,  false, false, false><<<gD, 256>>>(xn, w_q + wqkv_off, nullptr, q, MM, DD, DD);
        sgemm<true,  false, false, false><<<gD, 256>>>(xn, w_k + wqkv_off, nullptr, k, MM, DD, DD);
        sgemm<true,  false, false, false><<<gD, 256>>>(xn, w_v + wqkv_off, nullptr, v, MM, DD, DD);

        attn_kernel<<<gA, 64>>>(q, k, v, y);

        // x += y @ w_o   (w_o is [K=H*DV, N=D] row-major -> no transpose)
        sgemm<false, false, false, true ><<<gD, 256>>>(y, w_o + wo_off, nullptr, x, MM, DD, DD);

        ln_kernel<<<MM, 256>>>(x, xn, ln2_w + (size_t)l * DD, ln2_b + (size_t)l * DD);

        // h = relu(xn @ w1^T + b1)
        sgemm<true,  true,  true,  false><<<gH, 256>>>(xn, w1 + w1_off, b1 + (size_t)l * HDIM, h, MM, HDIM, DD);
        // x += h @ w2^T + b2
        sgemm<true,  true,  false, true ><<<gD, 256>>>(h, w2 + w2_off, b2 + (size_t)l * DD, x, MM, DD, HDIM);
    }

    // out = x @ ro_w^T + ro_b
    sgemm<true, true, false, false><<<gV, 256>>>(x, ro_w, ro_b, out, MM, VV, DD);
}

// round 3
// speedup vs baseline: 1.9508x; 1.9508x over previous
#include <cuda_runtime.h>
#include <cuda_bf16.h>
#include <math.h>
#include <stdint.h>

// ---------------------------------------------------------------------------
// Problem constants
// ---------------------------------------------------------------------------
#define BB   2
#define TT   2048
#define DD   1024
#define HH   16
#define HDIM 4096
#define VV   32000
#define LL   4
#define MM   (BB*TT)      // 4096 rows
#define QKVD (3*DD)       // 3072

// ---------------------------------------------------------------------------
// Static device scratch (no allocations allowed)
// ---------------------------------------------------------------------------
__device__ float g_x  [MM*DD];
__device__ float g_qkv[MM*QKVD];
__device__ __nv_bfloat16 g_xnh[MM*DD],  g_xnl[MM*DD];
__device__ __nv_bfloat16 g_yh [MM*DD],  g_yl [MM*DD];
__device__ __nv_bfloat16 g_hh [MM*HDIM], g_hl [MM*HDIM];
__device__ __nv_bfloat16 g_xh [MM*DD],  g_xl [MM*DD];
// split weights (recomputed every launch — weights are inputs)
__device__ __nv_bfloat16 g_wqkvh[LL*QKVD*DD], g_wqkvl[LL*QKVD*DD];
__device__ __nv_bfloat16 g_woh [LL*DD*DD],    g_wol [LL*DD*DD];
__device__ __nv_bfloat16 g_w1h [LL*HDIM*DD],  g_w1l [LL*HDIM*DD];
__device__ __nv_bfloat16 g_w2h [LL*DD*HDIM],  g_w2l [LL*DD*HDIM];
__device__ __nv_bfloat16 g_roh [VV*DD],       g_rol [VV*DD];

// ---------------------------------------------------------------------------
// helpers (base-target PTX only: cp.async, ldmatrix, mma.sync — NO tcgen05)
// ---------------------------------------------------------------------------
__device__ __forceinline__ uint32_t smem_u32(const void* p) {
    uint32_t a;
    asm("{ .reg .u64 t; cvta.to.shared.u64 t, %1; cvt.u32.u64 %0, t; }"
        : "=r"(a) : "l"(p));
    return a;
}
__device__ __forceinline__ void cp16(uint32_t dst, const void* src) {
    asm volatile("cp.async.cg.shared.global [%0], [%1], 16;" :: "r"(dst), "l"(src));
}
#define CP_COMMIT()  asm volatile("cp.async.commit_group;" ::: "memory")
#define CP_WAIT0()   asm volatile("cp.async.wait_group 0;" ::: "memory")
#define CP_WAIT1()   asm volatile("cp.async.wait_group 1;" ::: "memory")
#define CP_WAIT2()   asm volatile("cp.async.wait_group 2;" ::: "memory")

__device__ __forceinline__ void ldsm4(uint32_t& r0, uint32_t& r1,
                                      uint32_t& r2, uint32_t& r3, uint32_t addr) {
    asm volatile("ldmatrix.sync.aligned.m8n8.x4.shared.b16 {%0,%1,%2,%3}, [%4];"
                 : "=r"(r0), "=r"(r1), "=r"(r2), "=r"(r3) : "r"(addr));
}
__device__ __forceinline__ void mma16816(float* d, const uint32_t* a, const uint32_t* b) {
    asm volatile("mma.sync.aligned.m16n8k16.row.col.f32.bf16.bf16.f32 "
        "{%0,%1,%2,%3}, {%4,%5,%6,%7}, {%8,%9}, {%0,%1,%2,%3};"
        : "+f"(d[0]), "+f"(d[1]), "+f"(d[2]), "+f"(d[3])
        : "r"(a[0]), "r"(a[1]), "r"(a[2]), "r"(a[3]), "r"(b[0]), "r"(b[1]));
}
__device__ __forceinline__ void split2(float v, __nv_bfloat16& h, __nv_bfloat16& l) {
    h = __float2bfloat16(v);
    l = __float2bfloat16(v - __bfloat162float(h));
}

// ---------------------------------------------------------------------------
// HMMA split-bf16 GEMM: C[M,N] (+)= A[M,K] * B^T (+bias)(relu), B stored [N,K].
// CTA 128x128, 8 warps (each 32x64), K-chunk 32, 4-stage cp.async pipeline.
// Smem rows padded to 80B -> ldmatrix bank-conflict-free (bank stride 20/row).
// ---------------------------------------------------------------------------
#define STAGES  4
#define KC      32
#define PITCH   80u                   // bytes per 32-bf16 row (64B data + 16B pad)
#define TILE_B  (128u * PITCH)        // 10240 B per split-tile
#define STAGE_B (4u * TILE_B)         // Ah | Al | Bh | Bl = 40960 B
#define SMEM_B  (STAGES * STAGE_B)    // 163840 B

template<bool BIAS, bool RELU, bool ACCUM, bool SPLIT>
__global__ __launch_bounds__(256, 1)
void gemm_mma(const __nv_bfloat16* __restrict__ Ah, const __nv_bfloat16* __restrict__ Al,
              const __nv_bfloat16* __restrict__ Bh, const __nv_bfloat16* __restrict__ Bl,
              const float* __restrict__ bias,
              float* __restrict__ C,
              __nv_bfloat16* __restrict__ Ch, __nv_bfloat16* __restrict__ Cl,
              int M, int N, int K)
{
    extern __shared__ char smem_raw[];
    const uint32_t sb = smem_u32(smem_raw);

    const int tid  = threadIdx.x;
    const int wid  = tid >> 5;
    const int lane = tid & 31;
    const int row0 = blockIdx.y * 128;
    const int col0 = blockIdx.x * 128;
    const int NC   = K / KC;

    // stage loader: 2048 x 16B cp.async, 8 per thread
    auto load_stage = [&](int s) {
        const uint32_t stg = sb + (uint32_t)(s % STAGES) * STAGE_B;
        const int k0 = s * KC;
        #pragma unroll
        for (int i = 0; i < 8; i++) {
            int f = i * 256 + tid;          // 0..2047
            int split = f >> 9;             // 0:Ah 1:Al 2:Bh 3:Bl
            int rem   = f & 511;
            int r = rem >> 2, c = rem & 3;
            const __nv_bfloat16* base = (split == 0) ? Ah : (split == 1) ? Al
                                      : (split == 2) ? Bh : Bl;
            int grow = ((split < 2) ? row0 : col0) + r;
            const __nv_bfloat16* src = base + (size_t)grow * K + k0 + c * 8;
            uint32_t dst = stg + (uint32_t)split * TILE_B + (uint32_t)r * PITCH + c * 16;
            cp16(dst, src);
        }
        CP_COMMIT();
    };

    #pragma unroll
    for (int s = 0; s < STAGES - 1; s++) if (s < NC) load_stage(s);

    const int wm = wid & 3;    // 0..3 -> 32-row block
    const int wn = wid >> 2;   // 0..1 -> 64-col block

    float acc[2][8][4];
    #pragma unroll
    for (int a = 0; a < 2; a++)
        #pragma unroll
        for (int b = 0; b < 8; b++)
            #pragma unroll
            for (int c = 0; c < 4; c++) acc[a][b][c] = 0.f;

    for (int i = 0; i < NC; i++) {
        int kpend = NC - 1 - i; if (kpend > 2) kpend = 2;
        if (kpend == 0) CP_WAIT0(); else if (kpend == 1) CP_WAIT1(); else CP_WAIT2();
        __syncthreads();
        if (i + STAGES - 1 < NC) load_stage(i + STAGES - 1);

        const uint32_t stg = sb + (uint32_t)(i % STAGES) * STAGE_B;
        const uint32_t ah_b = stg;
        const uint32_t al_b = stg + TILE_B;
        const uint32_t bh_b = stg + 2u * TILE_B;
        const uint32_t bl_b = stg + 3u * TILE_B;

        #pragma unroll
        for (int ks = 0; ks < 2; ks++) {
            uint32_t ah[2][4], alr[2][4], bh[8][2], bl[8][2];
            const uint32_t a_coff = (uint32_t)ks * 32 + ((lane >> 4) << 4);
            #pragma unroll
            for (int mi = 0; mi < 2; mi++) {
                uint32_t r = (uint32_t)(wm * 32 + mi * 16 + (lane & 15));
                ldsm4(ah[mi][0],  ah[mi][1],  ah[mi][2],  ah[mi][3],  ah_b + r * PITCH + a_coff);
                ldsm4(alr[mi][0], alr[mi][1], alr[mi][2], alr[mi][3], al_b + r * PITCH + a_coff);
            }
            const uint32_t b_coff = (uint32_t)ks * 32 + (((lane >> 3) & 1) << 4);
            #pragma unroll
            for (int g = 0; g < 4; g++) {
                uint32_t r = (uint32_t)(wn * 64 + g * 16 + (lane & 7) + ((lane >> 4) << 3));
                ldsm4(bh[2*g][0], bh[2*g][1], bh[2*g+1][0], bh[2*g+1][1], bh_b + r * PITCH + b_coff);
                ldsm4(bl[2*g][0], bl[2*g][1], bl[2*g+1][0], bl[2*g+1][1], bl_b + r * PITCH + b_coff);
            }
            #pragma unroll
            for (int mi = 0; mi < 2; mi++)
                #pragma unroll
                for (int ni = 0; ni < 8; ni++) {
                    mma16816(acc[mi][ni], ah[mi],  bh[ni]);
                    mma16816(acc[mi][ni], ah[mi],  bl[ni]);
                    mma16816(acc[mi][ni], alr[mi], bh[ni]);
                }
        }
    }

    // ---- epilogue: acc reg (mi,ni)[c]; rows lane/4 (+8), cols 2*(lane%4)+{0,1}
    #pragma unroll
    for (int mi = 0; mi < 2; mi++) {
        #pragma unroll
        for (int rg = 0; rg < 2; rg++) {                 // reg pair 0/1 vs 2/3
            int r = row0 + wm * 32 + mi * 16 + (lane >> 2) + rg * 8;
            #pragma unroll
            for (int ni = 0; ni < 8; ni++) {
                int c = col0 + wn * 64 + ni * 8 + (lane & 3) * 2;
                float v0 = acc[mi][ni][rg * 2 + 0];
                float v1 = acc[mi][ni][rg * 2 + 1];
                if (BIAS)  { v0 += bias[c]; v1 += bias[c + 1]; }
                if (RELU)  { v0 = fmaxf(v0, 0.f); v1 = fmaxf(v1, 0.f); }
                if (ACCUM) {
                    float2 o = *(const float2*)&C[(size_t)r * N + c];
                    v0 += o.x; v1 += o.y;
                }
                if (SPLIT) {
                    __nv_bfloat16 h0, l0, h1, l1;
                    split2(v0, h0, l0); split2(v1, h1, l1);
                    *(__nv_bfloat162*)&Ch[(size_t)r * N + c] = __halves2bfloat162(h0, h1);
                    *(__nv_bfloat162*)&Cl[(size_t)r * N + c] = __halves2bfloat162(l0, l1);
                } else {
                    *(float2*)&C[(size_t)r * N + c] = make_float2(v0, v1);
                }
            }
        }
    }
}

// ---------------------------------------------------------------------------
// Embedding + positional encoding
// ---------------------------------------------------------------------------
__global__ void embed_kernel(const int* __restrict__ tokens,
                             const float* __restrict__ emb,
                             float* __restrict__ x)
{
    int idx = blockIdx.x * blockDim.x + threadIdx.x;
    if (idx >= MM * DD) return;
    int d  = idx & (DD - 1);
    int mt = idx >> 10;
    int b  = mt >> 11;
    int t  = mt & (TT - 1);
    int tok = (t == 0) ? 0 : tokens[b * TT + t - 1];
    int k = d & 1;
    double e = (double)(d - k) / (double)DD;
    float freq = (float)exp(-e * 11.512925464970229);   // LEN_MAX^-e
    float arg = (float)t * freq + 1.5707963267948966f * (float)k;
    x[idx] = emb[(size_t)tok * DD + d] + sinf(arg);
}

// ---------------------------------------------------------------------------
// LayerNorm -> split bf16 hi/lo output
// ---------------------------------------------------------------------------
__global__ __launch_bounds__(256) void ln_split_kernel(const float* __restrict__ x,
                                                       __nv_bfloat16* __restrict__ yh,
                                                       __nv_bfloat16* __restrict__ yl,
                                                       const float* __restrict__ w,
                                                       const float* __restrict__ b)
{
    __shared__ float red[8];
    int row = blockIdx.x;
    int tid = threadIdx.x;
    const float* xr = x + (size_t)row * DD;
    float4 xv = *(const float4*)&xr[tid * 4];

    float s = xv.x + xv.y + xv.z + xv.w;
    #pragma unroll
    for (int o = 16; o > 0; o >>= 1) s += __shfl_xor_sync(0xffffffffu, s, o);
    if ((tid & 31) == 0) red[tid >> 5] = s;
    __syncthreads();
    float tot = 0.f;
    #pragma unroll
    for (int i = 0; i < 8; i++) tot += red[i];
    float mean = tot * (1.0f / DD);
    __syncthreads();

    float dx0 = xv.x - mean, dx1 = xv.y - mean, dx2 = xv.z - mean, dx3 = xv.w - mean;
    float s2 = dx0*dx0 + dx1*dx1 + dx2*dx2 + dx3*dx3;
    #pragma unroll
    for (int o = 16; o > 0; o >>= 1) s2 += __shfl_xor_sync(0xffffffffu, s2, o);
    if ((tid & 31) == 0) red[tid >> 5] = s2;
    __syncthreads();
    float tot2 = 0.f;
    #pragma unroll
    for (int i = 0; i < 8; i++) tot2 += red[i];
    float inv = rsqrtf(tot2 * (1.0f / DD) + 1e-5f);

    int c = tid * 4;
    float4 wv = *(const float4*)&w[c];
    float4 bv = *(const float4*)&b[c];
    float o0 = dx0 * inv * wv.x + bv.x;
    float o1 = dx1 * inv * wv.y + bv.y;
    float o2 = dx2 * inv * wv.z + bv.z;
    float o3 = dx3 * inv * wv.w + bv.w;
    __nv_bfloat16 h0, l0, h1, l1, h2, l2, h3, l3;
    split2(o0, h0, l0); split2(o1, h1, l1); split2(o2, h2, l2); split2(o3, h3, l3);
    size_t off = (size_t)row * DD + c;
    *(__nv_bfloat162*)&yh[off]     = __halves2bfloat162(h0, h1);
    *(__nv_bfloat162*)&yh[off + 2] = __halves2bfloat162(h2, h3);
    *(__nv_bfloat162*)&yl[off]     = __halves2bfloat162(l0, l1);
    *(__nv_bfloat162*)&yl[off + 2] = __halves2bfloat162(l2, l3);
}

// ---------------------------------------------------------------------------
// Causal attention over packed qkv [M, 3072], outputs split bf16 y.
// ---------------------------------------------------------------------------
__global__ __launch_bounds__(64) void attn_kernel(const float* __restrict__ QKV,
                                                  __nv_bfloat16* __restrict__ Yh,
                                                  __nv_bfloat16* __restrict__ Yl)
{
    __shared__ float Ks[64][64];
    __shared__ float S[64][65];

    const int bh = blockIdx.y;
    const int b  = bh / HH;
    const int h  = bh % HH;
    const int qt = blockIdx.x;
    const int tid = threadIdx.x;
    const int t = qt * 64 + tid;
    const float scale = 0.125f;

    float q[64];
    const float* qp = QKV + (size_t)(b * TT + t) * QKVD + h * 64;
    #pragma unroll
    for (int i = 0; i < 64; i += 4) {
        float4 v4 = *(const float4*)&qp[i];
        q[i] = v4.x; q[i+1] = v4.y; q[i+2] = v4.z; q[i+3] = v4.w;
    }

    float m = -1e30f, l = 0.f;
    float acc[64];
    #pragma unroll
    for (int i = 0; i < 64; i++) acc[i] = 0.f;

    for (int s0 = 0; s0 <= qt * 64; s0 += 64) {
        __syncthreads();
        #pragma unroll
        for (int it = 0; it < 16; it++) {
            int f = it * 64 + tid;
            int r = f >> 4, c4 = (f & 15) << 2;
            *(float4*)&Ks[r][c4] =
                *(const float4*)&QKV[(size_t)(b * TT + s0 + r) * QKVD + DD + h * 64 + c4];
        }
        __syncthreads();

        float mx = -1e30f;
        for (int s = 0; s < 64; s++) {
            float d0 = 0.f, d1 = 0.f, d2 = 0.f, d3 = 0.f;
            #pragma unroll
            for (int i = 0; i < 64; i += 16) {
                float4 k0 = *(const float4*)&Ks[s][i];
                float4 k1 = *(const float4*)&Ks[s][i + 4];
                float4 k2 = *(const float4*)&Ks[s][i + 8];
                float4 k3 = *(const float4*)&Ks[s][i + 12];
                d0 += q[i+0]*k0.x + q[i+1]*k0.y + q[i+2]*k0.z + q[i+3]*k0.w;
                d1 += q[i+4]*k1.x + q[i+5]*k1.y + q[i+6]*k1.z + q[i+7]*k1.w;
                d2 += q[i+8]*k2.x + q[i+9]*k2.y + q[i+10]*k2.z + q[i+11]*k2.w;
                d3 += q[i+12]*k3.x + q[i+13]*k3.y + q[i+14]*k3.z + q[i+15]*k3.w;
            }
            float dsc = ((d0 + d1) + (d2 + d3)) * scale;
            if (s0 + s > t) dsc = -1e30f;
            S[tid][s] = dsc;
            mx = fmaxf(mx, dsc);
        }

        float mnew = fmaxf(m, mx);
        float corr = __expf(m - mnew);
        l *= corr;
        #pragma unroll
        for (int i = 0; i < 64; i++) acc[i] *= corr;
        float lsum = 0.f;
        for (int s = 0; s < 64; s++) {
            float p = __expf(S[tid][s] - mnew);
            S[tid][s] = p;
            lsum += p;
        }
        l += lsum;
        m = mnew;

        __syncthreads();
        #pragma unroll
        for (int it = 0; it < 16; it++) {
            int f = it * 64 + tid;
            int r = f >> 4, c4 = (f & 15) << 2;
            *(float4*)&Ks[r][c4] =
                *(const float4*)&QKV[(size_t)(b * TT + s0 + r) * QKVD + 2 * DD + h * 64 + c4];
        }
        __syncthreads();

        for (int s = 0; s < 64; s++) {
            float p = S[tid][s];
            #pragma unroll
            for (int i = 0; i < 64; i += 4) {
                float4 vv = *(const float4*)&Ks[s][i];
                acc[i+0] += p * vv.x;
                acc[i+1] += p * vv.y;
                acc[i+2] += p * vv.z;
                acc[i+3] += p * vv.w;
            }
        }
    }

    float inv = 1.0f / l;
    size_t yoff = (size_t)(b * TT + t) * DD + h * 64;
    #pragma unroll
    for (int i = 0; i < 64; i += 2) {
        __nv_bfloat16 h0, l0, h1, l1;
        split2(acc[i] * inv, h0, l0);
        split2(acc[i+1] * inv, h1, l1);
        *(__nv_bfloat162*)&Yh[yoff + i] = __halves2bfloat162(h0, h1);
        *(__nv_bfloat162*)&Yl[yoff + i] = __halves2bfloat162(l0, l1);
    }
}

// ---------------------------------------------------------------------------
// Weight / activation split kernels
// ---------------------------------------------------------------------------
__global__ void split_kernel(const float* __restrict__ s,
                             __nv_bfloat16* __restrict__ h,
                             __nv_bfloat16* __restrict__ l, int n)
{
    int i = blockIdx.x * blockDim.x + threadIdx.x;
    if (i >= n) return;
    __nv_bfloat16 hi, lo;
    split2(s[i], hi, lo);
    h[i] = hi; l[i] = lo;
}

__global__ void pack_qkv_kernel(const float* __restrict__ wq,
                                const float* __restrict__ wk,
                                const float* __restrict__ wv,
                                __nv_bfloat16* __restrict__ h,
                                __nv_bfloat16* __restrict__ l)
{
    int i = blockIdx.x * blockDim.x + threadIdx.x;
    const int per_layer = QKVD * DD;
    if (i >= LL * per_layer) return;
    int lyr = i / per_layer;
    int rem = i - lyr * per_layer;
    int row = rem >> 10;          // 0..3071
    int col = rem & 1023;
    int which = row >> 10;        // 0:q 1:k 2:v
    int srow  = row & 1023;
    const float* src = (which == 0) ? wq : ((which == 1) ? wk : wv);
    float v = src[(size_t)lyr * (DD * DD) + (size_t)srow * DD + col];
    __nv_bfloat16 hi, lo;
    split2(v, hi, lo);
    h[i] = hi; l[i] = lo;
}

__global__ void transpose_wo_kernel(const float* __restrict__ wo,
                                    __nv_bfloat16* __restrict__ h,
                                    __nv_bfloat16* __restrict__ l)
{
    int i = blockIdx.x * blockDim.x + threadIdx.x;
    if (i >= LL * DD * DD) return;
    int lyr = i >> 20;
    int rem = i & ((1 << 20) - 1);
    int nrow = rem >> 10;
    int kcol = rem & 1023;
    float v = wo[((size_t)lyr << 20) + ((size_t)kcol << 10) + nrow];
    __nv_bfloat16 hi, lo;
    split2(v, hi, lo);
    h[i] = hi; l[i] = lo;
}

// ---------------------------------------------------------------------------
// Launch
// ---------------------------------------------------------------------------
extern "C" void kernel_launch(void* const* d_in, const int* in_sizes, int n_in,
                              void* d_out, int out_size)
{
    const int*   tokens = (const int*)  d_in[0];
    const float* emb    = (const float*)d_in[1];
    const float* ln1_w  = (const float*)d_in[2];
    const float* ln1_b  = (const float*)d_in[3];
    const float* w_q    = (const float*)d_in[4];
    const float* w_k    = (const float*)d_in[5];
    const float* w_v    = (const float*)d_in[6];
    const float* w_o    = (const float*)d_in[7];
    const float* ln2_w  = (const float*)d_in[8];
    const float* ln2_b  = (const float*)d_in[9];
    const float* w1     = (const float*)d_in[10];
    const float* b1     = (const float*)d_in[11];
    const float* w2     = (const float*)d_in[12];
    const float* b2     = (const float*)d_in[13];
    const float* ro_w   = (const float*)d_in[14];
    const float* ro_b   = (const float*)d_in[15];
    float* out = (float*)d_out;

    float *x, *qkv;
    __nv_bfloat16 *xnh, *xnl, *yh, *yl, *hh, *hl, *xh, *xl;
    __nv_bfloat16 *wqkvh, *wqkvl, *woh, *wol, *w1h, *w1l, *w2h, *w2l, *roh, *rol;
    cudaGetSymbolAddress((void**)&x,    g_x);
    cudaGetSymbolAddress((void**)&qkv,  g_qkv);
    cudaGetSymbolAddress((void**)&xnh,  g_xnh);  cudaGetSymbolAddress((void**)&xnl, g_xnl);
    cudaGetSymbolAddress((void**)&yh,   g_yh);   cudaGetSymbolAddress((void**)&yl,  g_yl);
    cudaGetSymbolAddress((void**)&hh,   g_hh);   cudaGetSymbolAddress((void**)&hl,  g_hl);
    cudaGetSymbolAddress((void**)&xh,   g_xh);   cudaGetSymbolAddress((void**)&xl,  g_xl);
    cudaGetSymbolAddress((void**)&wqkvh,g_wqkvh);cudaGetSymbolAddress((void**)&wqkvl,g_wqkvl);
    cudaGetSymbolAddress((void**)&woh,  g_woh);  cudaGetSymbolAddress((void**)&wol, g_wol);
    cudaGetSymbolAddress((void**)&w1h,  g_w1h);  cudaGetSymbolAddress((void**)&w1l, g_w1l);
    cudaGetSymbolAddress((void**)&w2h,  g_w2h);  cudaGetSymbolAddress((void**)&w2l, g_w2l);
    cudaGetSymbolAddress((void**)&roh,  g_roh);  cudaGetSymbolAddress((void**)&rol, g_rol);

    cudaFuncSetAttribute((const void*)gemm_mma<false,false,false,false>,
                         cudaFuncAttributeMaxDynamicSharedMemorySize, SMEM_B);
    cudaFuncSetAttribute((const void*)gemm_mma<false,false,true,false>,
                         cudaFuncAttributeMaxDynamicSharedMemorySize, SMEM_B);
    cudaFuncSetAttribute((const void*)gemm_mma<true,true,false,true>,
                         cudaFuncAttributeMaxDynamicSharedMemorySize, SMEM_B);
    cudaFuncSetAttribute((const void*)gemm_mma<true,false,true,false>,
                         cudaFuncAttributeMaxDynamicSharedMemorySize, SMEM_B);
    cudaFuncSetAttribute((const void*)gemm_mma<true,false,false,false>,
                         cudaFuncAttributeMaxDynamicSharedMemorySize, SMEM_B);

    // weight conversion (every launch — weights are inputs)
    pack_qkv_kernel<<<(LL*QKVD*DD + 255)/256, 256>>>(w_q, w_k, w_v, wqkvh, wqkvl);
    transpose_wo_kernel<<<(LL*DD*DD + 255)/256, 256>>>(w_o, woh, wol);
    split_kernel<<<(LL*HDIM*DD + 255)/256, 256>>>(w1, w1h, w1l, LL*HDIM*DD);
    split_kernel<<<(LL*DD*HDIM + 255)/256, 256>>>(w2, w2h, w2l, LL*DD*HDIM);
    split_kernel<<<(VV*DD + 255)/256, 256>>>(ro_w, roh, rol, VV*DD);

    embed_kernel<<<(MM*DD + 255)/256, 256>>>(tokens, emb, x);

    const dim3 gQKV(QKVD/128, MM/128);    // 24 x 32
    const dim3 gD  (DD/128,   MM/128);    //  8 x 32
    const dim3 gH  (HDIM/128, MM/128);    // 32 x 32
    const dim3 gV  (VV/128,   MM/128);    // 250 x 32
    const dim3 gA  (TT/64, BB*HH);

    for (int l = 0; l < LL; l++) {
        const __nv_bfloat16* wqkvh_l = wqkvh + (size_t)l * QKVD * DD;
        const __nv_bfloat16* wqkvl_l = wqkvl + (size_t)l * QKVD * DD;
        const __nv_bfloat16* woh_l   = woh   + (size_t)l * DD * DD;
        const __nv_bfloat16* wol_l   = wol   + (size_t)l * DD * DD;
        const __nv_bfloat16* w1h_l   = w1h   + (size_t)l * HDIM * DD;
        const __nv_bfloat16* w1l_l   = w1l   + (size_t)l * HDIM * DD;
        const __nv_bfloat16* w2h_l   = w2h   + (size_t)l * DD * HDIM;
        const __nv_bfloat16* w2l_l   = w2l   + (size_t)l * DD * HDIM;

        ln_split_kernel<<<MM, 256>>>(x, xnh, xnl, ln1_w + (size_t)l*DD, ln1_b + (size_t)l*DD);

        // qkv = xn @ Wqkv^T   [4096, 3072]
        gemm_mma<false,false,false,false><<<gQKV, 256, SMEM_B>>>(
            xnh, xnl, wqkvh_l, wqkvl_l, nullptr, qkv, nullptr, nullptr, MM, QKVD, DD);

        attn_kernel<<<gA, 64>>>(qkv, yh, yl);

        // x += y @ w_o   (woT stored [N,K])
        gemm_mma<false,false,true,false><<<gD, 256, SMEM_B>>>(
            yh, yl, woh_l, wol_l, nullptr, x, nullptr, nullptr, MM, DD, DD);

        ln_split_kernel<<<MM, 256>>>(x, xnh, xnl, ln2_w + (size_t)l*DD, ln2_b + (size_t)l*DD);

        // h = relu(xn @ w1^T + b1) -> split bf16
        gemm_mma<true,true,false,true><<<gH, 256, SMEM_B>>>(
            xnh, xnl, w1h_l, w1l_l, b1 + (size_t)l*HDIM, nullptr, hh, hl, MM, HDIM, DD);

        // x += h @ w2^T + b2
        gemm_mma<true,false,true,false><<<gD, 256, SMEM_B>>>(
            hh, hl, w2h_l, w2l_l, b2 + (size_t)l*DD, x, nullptr, nullptr, MM, DD, HDIM);
    }

    // readout: out = x @ ro_w^T + ro_b
    split_kernel<<<(MM*DD + 255)/256, 256>>>(x, xh, xl, MM*DD);
    gemm_mma<true,false,false,false><<<gV, 256, SMEM_B>>>(
        xh, xl, roh, rol, ro_b, out, nullptr, nullptr, MM, VV, DD);
}

// round 4
// speedup vs baseline: 2.1087x; 1.0810x over previous
#include <cuda_runtime.h>
#include <cuda_bf16.h>
#include <math.h>
#include <stdint.h>

// ---------------------------------------------------------------------------
// Problem constants
// ---------------------------------------------------------------------------
#define BB   2
#define TT   2048
#define DD   1024
#define HH   16
#define HDIM 4096
#define VV   32000
#define LL   4
#define MM   (BB*TT)      // 4096 rows
#define QKVD (3*DD)       // 3072

// ---------------------------------------------------------------------------
// Static device scratch (no allocations allowed)
// ---------------------------------------------------------------------------
__device__ float g_x  [MM*DD];
__device__ float g_qkv[MM*QKVD];
__device__ __nv_bfloat16 g_xnh[MM*DD],  g_xnl[MM*DD];
__device__ __nv_bfloat16 g_yh [MM*DD],  g_yl [MM*DD];
__device__ __nv_bfloat16 g_hh [MM*HDIM], g_hl [MM*HDIM];
__device__ __nv_bfloat16 g_xh [MM*DD],  g_xl [MM*DD];
__device__ __nv_bfloat16 g_wqkvh[LL*QKVD*DD], g_wqkvl[LL*QKVD*DD];
__device__ __nv_bfloat16 g_woh [LL*DD*DD],    g_wol [LL*DD*DD];
__device__ __nv_bfloat16 g_w1h [LL*HDIM*DD],  g_w1l [LL*HDIM*DD];
__device__ __nv_bfloat16 g_w2h [LL*DD*HDIM],  g_w2l [LL*DD*HDIM];
__device__ __nv_bfloat16 g_roh [VV*DD],       g_rol [VV*DD];

// ---------------------------------------------------------------------------
// helpers (base-target PTX only: cp.async, ldmatrix, mma.sync)
// ---------------------------------------------------------------------------
__device__ __forceinline__ uint32_t smem_u32(const void* p) {
    uint32_t a;
    asm("{ .reg .u64 t; cvta.to.shared.u64 t, %1; cvt.u32.u64 %0, t; }"
        : "=r"(a) : "l"(p));
    return a;
}
__device__ __forceinline__ void cp16(uint32_t dst, const void* src) {
    asm volatile("cp.async.cg.shared.global [%0], [%1], 16;" :: "r"(dst), "l"(src));
}
#define CP_COMMIT()  asm volatile("cp.async.commit_group;" ::: "memory")
#define CP_WAIT0()   asm volatile("cp.async.wait_group 0;" ::: "memory")
#define CP_WAIT1()   asm volatile("cp.async.wait_group 1;" ::: "memory")

__device__ __forceinline__ void ldsm4(uint32_t& r0, uint32_t& r1,
                                      uint32_t& r2, uint32_t& r3, uint32_t addr) {
    asm volatile("ldmatrix.sync.aligned.m8n8.x4.shared.b16 {%0,%1,%2,%3}, [%4];"
                 : "=r"(r0), "=r"(r1), "=r"(r2), "=r"(r3) : "r"(addr));
}
__device__ __forceinline__ void mma16816(float* d, const uint32_t* a, const uint32_t* b) {
    asm volatile("mma.sync.aligned.m16n8k16.row.col.f32.bf16.bf16.f32 "
        "{%0,%1,%2,%3}, {%4,%5,%6,%7}, {%8,%9}, {%0,%1,%2,%3};"
        : "+f"(d[0]), "+f"(d[1]), "+f"(d[2]), "+f"(d[3])
        : "r"(a[0]), "r"(a[1]), "r"(a[2]), "r"(a[3]), "r"(b[0]), "r"(b[1]));
}
__device__ __forceinline__ void split2(float v, __nv_bfloat16& h, __nv_bfloat16& l) {
    h = __float2bfloat16(v);
    l = __float2bfloat16(v - __bfloat162float(h));
}

// ---------------------------------------------------------------------------
// HMMA split-bf16 GEMM: C[M,N] (+)= A[M,K] * B^T (+bias)(relu), B stored [N,K].
// CTA 128(M)x256(N), 8 warps as 2(m)x4(n) -> 64x64 warp tiles.
// K-chunk 32, 3-stage cp.async pipeline, one __syncthreads per chunk.
// grid.x = M-block (fast), grid.y = N-block (slow) -> weight L2 reuse.
// ---------------------------------------------------------------------------
#define STAGES  3
#define KC      32
#define PITCH   80u                    // 64B data + 16B pad per 32-bf16 row
#define A_TILE  (128u * PITCH)         // 10240
#define B_TILE  (256u * PITCH)         // 20480
#define STAGE_B (2u*A_TILE + 2u*B_TILE)// 61440: Ah | Al | Bh | Bl
#define SMEM_B  (STAGES * STAGE_B)     // 184320

template<bool BIAS, bool RELU, bool ACCUM, bool SPLIT>
__global__ __launch_bounds__(256, 1)
void gemm_mma(const __nv_bfloat16* __restrict__ Ah, const __nv_bfloat16* __restrict__ Al,
              const __nv_bfloat16* __restrict__ Bh, const __nv_bfloat16* __restrict__ Bl,
              const float* __restrict__ bias,
              float* __restrict__ C,
              __nv_bfloat16* __restrict__ Ch, __nv_bfloat16* __restrict__ Cl,
              int M, int N, int K)
{
    extern __shared__ char smem_raw[];
    const uint32_t sb = smem_u32(smem_raw);

    const int tid  = threadIdx.x;
    const int wid  = tid >> 5;
    const int lane = tid & 31;
    const int row0 = blockIdx.x * 128;     // M fast
    const int col0 = blockIdx.y * 256;     // N slow
    const int NC   = K / KC;

    // stage loader: A 1024 cp16 (4/thread), B 2048 cp16 (8/thread)
    auto load_stage = [&](int s) {
        const uint32_t stg = sb + (uint32_t)(s % STAGES) * STAGE_B;
        const int k0 = s * KC;
        #pragma unroll
        for (int i = 0; i < 4; i++) {
            int f = i * 256 + tid;              // 0..1023
            int sub = f >> 9;                   // 0:Ah 1:Al
            int rem = f & 511;
            int r = rem >> 2, c = rem & 3;
            const __nv_bfloat16* src = ((sub == 0) ? Ah : Al)
                                     + (size_t)(row0 + r) * K + k0 + c * 8;
            cp16(stg + (uint32_t)sub * A_TILE + (uint32_t)r * PITCH + c * 16, src);
        }
        #pragma unroll
        for (int i = 0; i < 8; i++) {
            int f = i * 256 + tid;              // 0..2047
            int sub = f >> 10;                  // 0:Bh 1:Bl
            int rem = f & 1023;
            int r = rem >> 2, c = rem & 3;
            const __nv_bfloat16* src = ((sub == 0) ? Bh : Bl)
                                     + (size_t)(col0 + r) * K + k0 + c * 8;
            cp16(stg + 2u*A_TILE + (uint32_t)sub * B_TILE + (uint32_t)r * PITCH + c * 16, src);
        }
        CP_COMMIT();
    };

    load_stage(0);
    if (NC > 1) load_stage(1);

    const int wm = wid >> 2;   // 0..1 -> 64-row block
    const int wn = wid & 3;    // 0..3 -> 64-col block

    float acc[4][8][4];
    #pragma unroll
    for (int a = 0; a < 4; a++)
        #pragma unroll
        for (int b = 0; b < 8; b++)
            #pragma unroll
            for (int c = 0; c < 4; c++) acc[a][b][c] = 0.f;

    for (int i = 0; i < NC; i++) {
        if (i < NC - 1) CP_WAIT1(); else CP_WAIT0();
        __syncthreads();
        if (i + 2 < NC) load_stage(i + 2);   // overwrites chunk i-1's stage (done)

        const uint32_t stg  = sb + (uint32_t)(i % STAGES) * STAGE_B;
        const uint32_t ah_b = stg;
        const uint32_t al_b = stg + A_TILE;
        const uint32_t bh_b = stg + 2u*A_TILE;
        const uint32_t bl_b = stg + 2u*A_TILE + B_TILE;

        #pragma unroll
        for (int ks = 0; ks < 2; ks++) {
            uint32_t ah[4][4], al[4][4], bf[8][2];
            const uint32_t a_coff = (uint32_t)ks * 32 + ((lane >> 4) << 4);
            #pragma unroll
            for (int mi = 0; mi < 4; mi++) {
                uint32_t r = (uint32_t)(wm * 64 + mi * 16 + (lane & 15));
                ldsm4(ah[mi][0], ah[mi][1], ah[mi][2], ah[mi][3], ah_b + r * PITCH + a_coff);
                ldsm4(al[mi][0], al[mi][1], al[mi][2], al[mi][3], al_b + r * PITCH + a_coff);
            }
            const uint32_t b_coff = (uint32_t)ks * 32 + (((lane >> 3) & 1) << 4);
            #pragma unroll
            for (int g = 0; g < 4; g++) {
                uint32_t r = (uint32_t)(wn * 64 + g * 16 + (lane & 7) + ((lane >> 4) << 3));
                ldsm4(bf[2*g][0], bf[2*g][1], bf[2*g+1][0], bf[2*g+1][1], bh_b + r * PITCH + b_coff);
            }
            #pragma unroll
            for (int mi = 0; mi < 4; mi++)
                #pragma unroll
                for (int ni = 0; ni < 8; ni++) {
                    mma16816(acc[mi][ni], ah[mi], bf[ni]);
                    mma16816(acc[mi][ni], al[mi], bf[ni]);
                }
            // reload B-lo over bf regs
            #pragma unroll
            for (int g = 0; g < 4; g++) {
                uint32_t r = (uint32_t)(wn * 64 + g * 16 + (lane & 7) + ((lane >> 4) << 3));
                ldsm4(bf[2*g][0], bf[2*g][1], bf[2*g+1][0], bf[2*g+1][1], bl_b + r * PITCH + b_coff);
            }
            #pragma unroll
            for (int mi = 0; mi < 4; mi++)
                #pragma unroll
                for (int ni = 0; ni < 8; ni++)
                    mma16816(acc[mi][ni], ah[mi], bf[ni]);
        }
    }

    // ---- epilogue ----
    #pragma unroll
    for (int mi = 0; mi < 4; mi++) {
        #pragma unroll
        for (int rg = 0; rg < 2; rg++) {
            int r = row0 + wm * 64 + mi * 16 + (lane >> 2) + rg * 8;
            #pragma unroll
            for (int ni = 0; ni < 8; ni++) {
                int c = col0 + wn * 64 + ni * 8 + (lane & 3) * 2;
                float v0 = acc[mi][ni][rg * 2 + 0];
                float v1 = acc[mi][ni][rg * 2 + 1];
                if (BIAS)  { v0 += bias[c]; v1 += bias[c + 1]; }
                if (RELU)  { v0 = fmaxf(v0, 0.f); v1 = fmaxf(v1, 0.f); }
                if (ACCUM) {
                    float2 o = *(const float2*)&C[(size_t)r * N + c];
                    v0 += o.x; v1 += o.y;
                }
                if (SPLIT) {
                    __nv_bfloat16 h0, l0, h1, l1;
                    split2(v0, h0, l0); split2(v1, h1, l1);
                    *(__nv_bfloat162*)&Ch[(size_t)r * N + c] = __halves2bfloat162(h0, h1);
                    *(__nv_bfloat162*)&Cl[(size_t)r * N + c] = __halves2bfloat162(l0, l1);
                } else {
                    *(float2*)&C[(size_t)r * N + c] = make_float2(v0, v1);
                }
            }
        }
    }
}

// ---------------------------------------------------------------------------
// Embedding + positional encoding
// ---------------------------------------------------------------------------
__global__ void embed_kernel(const int* __restrict__ tokens,
                             const float* __restrict__ emb,
                             float* __restrict__ x)
{
    int idx = blockIdx.x * blockDim.x + threadIdx.x;
    if (idx >= MM * DD) return;
    int d  = idx & (DD - 1);
    int mt = idx >> 10;
    int b  = mt >> 11;
    int t  = mt & (TT - 1);
    int tok = (t == 0) ? 0 : tokens[b * TT + t - 1];
    int k = d & 1;
    double e = (double)(d - k) / (double)DD;
    float freq = (float)exp(-e * 11.512925464970229);   // LEN_MAX^-e
    float arg = (float)t * freq + 1.5707963267948966f * (float)k;
    x[idx] = emb[(size_t)tok * DD + d] + sinf(arg);
}

// ---------------------------------------------------------------------------
// LayerNorm -> split bf16 hi/lo output
// ---------------------------------------------------------------------------
__global__ __launch_bounds__(256) void ln_split_kernel(const float* __restrict__ x,
                                                       __nv_bfloat16* __restrict__ yh,
                                                       __nv_bfloat16* __restrict__ yl,
                                                       const float* __restrict__ w,
                                                       const float* __restrict__ b)
{
    __shared__ float red[8];
    int row = blockIdx.x;
    int tid = threadIdx.x;
    const float* xr = x + (size_t)row * DD;
    float4 xv = *(const float4*)&xr[tid * 4];

    float s = xv.x + xv.y + xv.z + xv.w;
    #pragma unroll
    for (int o = 16; o > 0; o >>= 1) s += __shfl_xor_sync(0xffffffffu, s, o);
    if ((tid & 31) == 0) red[tid >> 5] = s;
    __syncthreads();
    float tot = 0.f;
    #pragma unroll
    for (int i = 0; i < 8; i++) tot += red[i];
    float mean = tot * (1.0f / DD);
    __syncthreads();

    float dx0 = xv.x - mean, dx1 = xv.y - mean, dx2 = xv.z - mean, dx3 = xv.w - mean;
    float s2 = dx0*dx0 + dx1*dx1 + dx2*dx2 + dx3*dx3;
    #pragma unroll
    for (int o = 16; o > 0; o >>= 1) s2 += __shfl_xor_sync(0xffffffffu, s2, o);
    if ((tid & 31) == 0) red[tid >> 5] = s2;
    __syncthreads();
    float tot2 = 0.f;
    #pragma unroll
    for (int i = 0; i < 8; i++) tot2 += red[i];
    float inv = rsqrtf(tot2 * (1.0f / DD) + 1e-5f);

    int c = tid * 4;
    float4 wv = *(const float4*)&w[c];
    float4 bv = *(const float4*)&b[c];
    float o0 = dx0 * inv * wv.x + bv.x;
    float o1 = dx1 * inv * wv.y + bv.y;
    float o2 = dx2 * inv * wv.z + bv.z;
    float o3 = dx3 * inv * wv.w + bv.w;
    __nv_bfloat16 h0, l0, h1, l1, h2, l2, h3, l3;
    split2(o0, h0, l0); split2(o1, h1, l1); split2(o2, h2, l2); split2(o3, h3, l3);
    size_t off = (size_t)row * DD + c;
    *(__nv_bfloat162*)&yh[off]     = __halves2bfloat162(h0, h1);
    *(__nv_bfloat162*)&yh[off + 2] = __halves2bfloat162(h2, h3);
    *(__nv_bfloat162*)&yl[off]     = __halves2bfloat162(l0, l1);
    *(__nv_bfloat162*)&yl[off + 2] = __halves2bfloat162(l2, l3);
}

// ---------------------------------------------------------------------------
// Causal attention over packed qkv [M, 3072], outputs split bf16 y.
// ---------------------------------------------------------------------------
__global__ __launch_bounds__(64) void attn_kernel(const float* __restrict__ QKV,
                                                  __nv_bfloat16* __restrict__ Yh,
                                                  __nv_bfloat16* __restrict__ Yl)
{
    __shared__ float Ks[64][64];
    __shared__ float S[64][65];

    const int bh = blockIdx.y;
    const int b  = bh / HH;
    const int h  = bh % HH;
    const int qt = blockIdx.x;
    const int tid = threadIdx.x;
    const int t = qt * 64 + tid;
    const float scale = 0.125f;

    float q[64];
    const float* qp = QKV + (size_t)(b * TT + t) * QKVD + h * 64;
    #pragma unroll
    for (int i = 0; i < 64; i += 4) {
        float4 v4 = *(const float4*)&qp[i];
        q[i] = v4.x; q[i+1] = v4.y; q[i+2] = v4.z; q[i+3] = v4.w;
    }

    float m = -1e30f, l = 0.f;
    float acc[64];
    #pragma unroll
    for (int i = 0; i < 64; i++) acc[i] = 0.f;

    for (int s0 = 0; s0 <= qt * 64; s0 += 64) {
        __syncthreads();
        #pragma unroll
        for (int it = 0; it < 16; it++) {
            int f = it * 64 + tid;
            int r = f >> 4, c4 = (f & 15) << 2;
            *(float4*)&Ks[r][c4] =
                *(const float4*)&QKV[(size_t)(b * TT + s0 + r) * QKVD + DD + h * 64 + c4];
        }
        __syncthreads();

        float mx = -1e30f;
        for (int s = 0; s < 64; s++) {
            float d0 = 0.f, d1 = 0.f, d2 = 0.f, d3 = 0.f;
            #pragma unroll
            for (int i = 0; i < 64; i += 16) {
                float4 k0 = *(const float4*)&Ks[s][i];
                float4 k1 = *(const float4*)&Ks[s][i + 4];
                float4 k2 = *(const float4*)&Ks[s][i + 8];
                float4 k3 = *(const float4*)&Ks[s][i + 12];
                d0 += q[i+0]*k0.x + q[i+1]*k0.y + q[i+2]*k0.z + q[i+3]*k0.w;
                d1 += q[i+4]*k1.x + q[i+5]*k1.y + q[i+6]*k1.z + q[i+7]*k1.w;
                d2 += q[i+8]*k2.x + q[i+9]*k2.y + q[i+10]*k2.z + q[i+11]*k2.w;
                d3 += q[i+12]*k3.x + q[i+13]*k3.y + q[i+14]*k3.z + q[i+15]*k3.w;
            }
            float dsc = ((d0 + d1) + (d2 + d3)) * scale;
            if (s0 + s > t) dsc = -1e30f;
            S[tid][s] = dsc;
            mx = fmaxf(mx, dsc);
        }

        float mnew = fmaxf(m, mx);
        float corr = __expf(m - mnew);
        l *= corr;
        #pragma unroll
        for (int i = 0; i < 64; i++) acc[i] *= corr;
        float lsum = 0.f;
        for (int s = 0; s < 64; s++) {
            float p = __expf(S[tid][s] - mnew);
            S[tid][s] = p;
            lsum += p;
        }
        l += lsum;
        m = mnew;

        __syncthreads();
        #pragma unroll
        for (int it = 0; it < 16; it++) {
            int f = it * 64 + tid;
            int r = f >> 4, c4 = (f & 15) << 2;
            *(float4*)&Ks[r][c4] =
                *(const float4*)&QKV[(size_t)(b * TT + s0 + r) * QKVD + 2 * DD + h * 64 + c4];
        }
        __syncthreads();

        for (int s = 0; s < 64; s++) {
            float p = S[tid][s];
            #pragma unroll
            for (int i = 0; i < 64; i += 4) {
                float4 vv = *(const float4*)&Ks[s][i];
                acc[i+0] += p * vv.x;
                acc[i+1] += p * vv.y;
                acc[i+2] += p * vv.z;
                acc[i+3] += p * vv.w;
            }
        }
    }

    float inv = 1.0f / l;
    size_t yoff = (size_t)(b * TT + t) * DD + h * 64;
    #pragma unroll
    for (int i = 0; i < 64; i += 2) {
        __nv_bfloat16 h0, l0, h1, l1;
        split2(acc[i] * inv, h0, l0);
        split2(acc[i+1] * inv, h1, l1);
        *(__nv_bfloat162*)&Yh[yoff + i] = __halves2bfloat162(h0, h1);
        *(__nv_bfloat162*)&Yl[yoff + i] = __halves2bfloat162(l0, l1);
    }
}

// ---------------------------------------------------------------------------
// Weight / activation split kernels (vectorized x4)
// ---------------------------------------------------------------------------
__global__ void split_kernel(const float* __restrict__ s,
                             __nv_bfloat16* __restrict__ h,
                             __nv_bfloat16* __restrict__ l, int n4)
{
    int i = blockIdx.x * blockDim.x + threadIdx.x;
    if (i >= n4) return;
    float4 v = *(const float4*)&s[i * 4];
    __nv_bfloat16 h0, l0, h1, l1, h2, l2, h3, l3;
    split2(v.x, h0, l0); split2(v.y, h1, l1); split2(v.z, h2, l2); split2(v.w, h3, l3);
    *(__nv_bfloat162*)&h[i*4]   = __halves2bfloat162(h0, h1);
    *(__nv_bfloat162*)&h[i*4+2] = __halves2bfloat162(h2, h3);
    *(__nv_bfloat162*)&l[i*4]   = __halves2bfloat162(l0, l1);
    *(__nv_bfloat162*)&l[i*4+2] = __halves2bfloat162(l2, l3);
}

__global__ void pack_qkv_kernel(const float* __restrict__ wq,
                                const float* __restrict__ wk,
                                const float* __restrict__ wv,
                                __nv_bfloat16* __restrict__ h,
                                __nv_bfloat16* __restrict__ l)
{
    int i = blockIdx.x * blockDim.x + threadIdx.x;   // x4 elements
    const int per_layer4 = QKVD * DD / 4;
    if (i >= LL * per_layer4) return;
    int lyr = i / per_layer4;
    int rem = i - lyr * per_layer4;          // element4 within layer
    int row = rem >> 8;                      // 0..3071 (256 float4 per row)
    int c4  = rem & 255;
    int which = row >> 10;
    int srow  = row & 1023;
    const float* src = (which == 0) ? wq : ((which == 1) ? wk : wv);
    float4 v = *(const float4*)&src[(size_t)lyr * (DD*DD) + (size_t)srow * DD + c4 * 4];
    __nv_bfloat16 h0, l0, h1, l1, h2, l2, h3, l3;
    split2(v.x, h0, l0); split2(v.y, h1, l1); split2(v.z, h2, l2); split2(v.w, h3, l3);
    size_t o = (size_t)i * 4;
    *(__nv_bfloat162*)&h[o]   = __halves2bfloat162(h0, h1);
    *(__nv_bfloat162*)&h[o+2] = __halves2bfloat162(h2, h3);
    *(__nv_bfloat162*)&l[o]   = __halves2bfloat162(l0, l1);
    *(__nv_bfloat162*)&l[o+2] = __halves2bfloat162(l2, l3);
}

__global__ void transpose_wo_kernel(const float* __restrict__ wo,
                                    __nv_bfloat16* __restrict__ h,
                                    __nv_bfloat16* __restrict__ l)
{
    int i = blockIdx.x * blockDim.x + threadIdx.x;
    if (i >= LL * DD * DD) return;
    int lyr = i >> 20;
    int rem = i & ((1 << 20) - 1);
    int nrow = rem >> 10;
    int kcol = rem & 1023;
    float v = wo[((size_t)lyr << 20) + ((size_t)kcol << 10) + nrow];
    __nv_bfloat16 hi, lo;
    split2(v, hi, lo);
    h[i] = hi; l[i] = lo;
}

// ---------------------------------------------------------------------------
// Launch
// ---------------------------------------------------------------------------
extern "C" void kernel_launch(void* const* d_in, const int* in_sizes, int n_in,
                              void* d_out, int out_size)
{
    const int*   tokens = (const int*)  d_in[0];
    const float* emb    = (const float*)d_in[1];
    const float* ln1_w  = (const float*)d_in[2];
    const float* ln1_b  = (const float*)d_in[3];
    const float* w_q    = (const float*)d_in[4];
    const float* w_k    = (const float*)d_in[5];
    const float* w_v    = (const float*)d_in[6];
    const float* w_o    = (const float*)d_in[7];
    const float* ln2_w  = (const float*)d_in[8];
    const float* ln2_b  = (const float*)d_in[9];
    const float* w1     = (const float*)d_in[10];
    const float* b1     = (const float*)d_in[11];
    const float* w2     = (const float*)d_in[12];
    const float* b2     = (const float*)d_in[13];
    const float* ro_w   = (const float*)d_in[14];
    const float* ro_b   = (const float*)d_in[15];
    float* out = (float*)d_out;

    float *x, *qkv;
    __nv_bfloat16 *xnh, *xnl, *yh, *yl, *hh, *hl, *xh, *xl;
    __nv_bfloat16 *wqkvh, *wqkvl, *woh, *wol, *w1h, *w1l, *w2h, *w2l, *roh, *rol;
    cudaGetSymbolAddress((void**)&x,    g_x);
    cudaGetSymbolAddress((void**)&qkv,  g_qkv);
    cudaGetSymbolAddress((void**)&xnh,  g_xnh);  cudaGetSymbolAddress((void**)&xnl, g_xnl);
    cudaGetSymbolAddress((void**)&yh,   g_yh);   cudaGetSymbolAddress((void**)&yl,  g_yl);
    cudaGetSymbolAddress((void**)&hh,   g_hh);   cudaGetSymbolAddress((void**)&hl,  g_hl);
    cudaGetSymbolAddress((void**)&xh,   g_xh);   cudaGetSymbolAddress((void**)&xl,  g_xl);
    cudaGetSymbolAddress((void**)&wqkvh,g_wqkvh);cudaGetSymbolAddress((void**)&wqkvl,g_wqkvl);
    cudaGetSymbolAddress((void**)&woh,  g_woh);  cudaGetSymbolAddress((void**)&wol, g_wol);
    cudaGetSymbolAddress((void**)&w1h,  g_w1h);  cudaGetSymbolAddress((void**)&w1l, g_w1l);
    cudaGetSymbolAddress((void**)&w2h,  g_w2h);  cudaGetSymbolAddress((void**)&w2l, g_w2l);
    cudaGetSymbolAddress((void**)&roh,  g_roh);  cudaGetSymbolAddress((void**)&rol, g_rol);

    cudaFuncSetAttribute((const void*)gemm_mma<false,false,false,false>,
                         cudaFuncAttributeMaxDynamicSharedMemorySize, SMEM_B);
    cudaFuncSetAttribute((const void*)gemm_mma<false,false,true,false>,
                         cudaFuncAttributeMaxDynamicSharedMemorySize, SMEM_B);
    cudaFuncSetAttribute((const void*)gemm_mma<true,true,false,true>,
                         cudaFuncAttributeMaxDynamicSharedMemorySize, SMEM_B);
    cudaFuncSetAttribute((const void*)gemm_mma<true,false,true,false>,
                         cudaFuncAttributeMaxDynamicSharedMemorySize, SMEM_B);
    cudaFuncSetAttribute((const void*)gemm_mma<true,false,false,false>,
                         cudaFuncAttributeMaxDynamicSharedMemorySize, SMEM_B);

    // weight conversion (every launch — weights are inputs)
    pack_qkv_kernel<<<(LL*QKVD*DD/4 + 255)/256, 256>>>(w_q, w_k, w_v, wqkvh, wqkvl);
    transpose_wo_kernel<<<(LL*DD*DD + 255)/256, 256>>>(w_o, woh, wol);
    split_kernel<<<(LL*HDIM*DD/4 + 255)/256, 256>>>(w1, w1h, w1l, LL*HDIM*DD/4);
    split_kernel<<<(LL*DD*HDIM/4 + 255)/256, 256>>>(w2, w2h, w2l, LL*DD*HDIM/4);
    split_kernel<<<(VV*DD/4 + 255)/256, 256>>>(ro_w, roh, rol, VV*DD/4);

    embed_kernel<<<(MM*DD + 255)/256, 256>>>(tokens, emb, x);

    // grid: x = M-block (fast), y = N-block (slow)
    const dim3 gQKV(MM/128, QKVD/256);    // 32 x 12
    const dim3 gD  (MM/128, DD/256);      // 32 x 4
    const dim3 gH  (MM/128, HDIM/256);    // 32 x 16
    const dim3 gV  (MM/128, VV/256);      // 32 x 125
    const dim3 gA  (TT/64, BB*HH);

    for (int l = 0; l < LL; l++) {
        const __nv_bfloat16* wqkvh_l = wqkvh + (size_t)l * QKVD * DD;
        const __nv_bfloat16* wqkvl_l = wqkvl + (size_t)l * QKVD * DD;
        const __nv_bfloat16* woh_l   = woh   + (size_t)l * DD * DD;
        const __nv_bfloat16* wol_l   = wol   + (size_t)l * DD * DD;
        const __nv_bfloat16* w1h_l   = w1h   + (size_t)l * HDIM * DD;
        const __nv_bfloat16* w1l_l   = w1l   + (size_t)l * HDIM * DD;
        const __nv_bfloat16* w2h_l   = w2h   + (size_t)l * DD * HDIM;
        const __nv_bfloat16* w2l_l   = w2l   + (size_t)l * DD * HDIM;

        ln_split_kernel<<<MM, 256>>>(x, xnh, xnl, ln1_w + (size_t)l*DD, ln1_b + (size_t)l*DD);

        gemm_mma<false,false,false,false><<<gQKV, 256, SMEM_B>>>(
            xnh, xnl, wqkvh_l, wqkvl_l, nullptr, qkv, nullptr, nullptr, MM, QKVD, DD);

        attn_kernel<<<gA, 64>>>(qkv, yh, yl);

        gemm_mma<false,false,true,false><<<gD, 256, SMEM_B>>>(
            yh, yl, woh_l, wol_l, nullptr, x, nullptr, nullptr, MM, DD, DD);

        ln_split_kernel<<<MM, 256>>>(x, xnh, xnl, ln2_w + (size_t)l*DD, ln2_b + (size_t)l*DD);

        gemm_mma<true,true,false,true><<<gH, 256, SMEM_B>>>(
            xnh, xnl, w1h_l, w1l_l, b1 + (size_t)l*HDIM, nullptr, hh, hl, MM, HDIM, DD);

        gemm_mma<true,false,true,false><<<gD, 256, SMEM_B>>>(
            hh, hl, w2h_l, w2l_l, b2 + (size_t)l*DD, x, nullptr, nullptr, MM, DD, HDIM);
    }

    split_kernel<<<(MM*DD/4 + 255)/256, 256>>>(x, xh, xl, MM*DD/4);
    gemm_mma<true,false,false,false><<<gV, 256, SMEM_B>>>(
        xh, xl, roh, rol, ro_b, out, nullptr, nullptr, MM, VV, DD);
}

// round 5
// speedup vs baseline: 2.5761x; 1.2217x over previous
#include <cuda_runtime.h>
#include <cuda_fp16.h>
#include <math.h>
#include <stdint.h>

// ---------------------------------------------------------------------------
// Problem constants
// ---------------------------------------------------------------------------
#define BB   2
#define TT   2048
#define DD   1024
#define HH   16
#define HDIM 4096
#define VV   32000
#define LL   4
#define MM   (BB*TT)      // 4096 rows
#define QKVD (3*DD)       // 3072

// ---------------------------------------------------------------------------
// Static device scratch (no allocations allowed)
// ---------------------------------------------------------------------------
__device__ float g_x  [MM*DD];
__device__ float g_qkv[MM*QKVD];
__device__ __half g_xnh[MM*DD],  g_xnl[MM*DD];
__device__ __half g_yh [MM*DD],  g_yl [MM*DD];
__device__ __half g_hh [MM*HDIM], g_hl [MM*HDIM];
__device__ __half g_xh [MM*DD],  g_xl [MM*DD];
// single-term fp16 weights (recomputed every launch — weights are inputs)
__device__ __half g_wqkv[LL*QKVD*DD];
__device__ __half g_wo  [LL*DD*DD];
__device__ __half g_w1  [LL*HDIM*DD];
__device__ __half g_w2  [LL*DD*HDIM];
__device__ __half g_ro  [VV*DD];

// ---------------------------------------------------------------------------
// helpers (base-target PTX only: cp.async, ldmatrix, mma.sync)
// ---------------------------------------------------------------------------
__device__ __forceinline__ uint32_t smem_u32(const void* p) {
    uint32_t a;
    asm("{ .reg .u64 t; cvta.to.shared.u64 t, %1; cvt.u32.u64 %0, t; }"
        : "=r"(a) : "l"(p));
    return a;
}
__device__ __forceinline__ void cp16(uint32_t dst, const void* src) {
    asm volatile("cp.async.cg.shared.global [%0], [%1], 16;" :: "r"(dst), "l"(src));
}
#define CP_COMMIT()  asm volatile("cp.async.commit_group;" ::: "memory")
#define CP_WAIT0()   asm volatile("cp.async.wait_group 0;" ::: "memory")
#define CP_WAIT1()   asm volatile("cp.async.wait_group 1;" ::: "memory")
#define CP_WAIT2()   asm volatile("cp.async.wait_group 2;" ::: "memory")

__device__ __forceinline__ void ldsm4(uint32_t& r0, uint32_t& r1,
                                      uint32_t& r2, uint32_t& r3, uint32_t addr) {
    asm volatile("ldmatrix.sync.aligned.m8n8.x4.shared.b16 {%0,%1,%2,%3}, [%4];"
                 : "=r"(r0), "=r"(r1), "=r"(r2), "=r"(r3) : "r"(addr));
}
__device__ __forceinline__ void mma16816(float* d, const uint32_t* a, const uint32_t* b) {
    asm volatile("mma.sync.aligned.m16n8k16.row.col.f32.f16.f16.f32 "
        "{%0,%1,%2,%3}, {%4,%5,%6,%7}, {%8,%9}, {%0,%1,%2,%3};"
        : "+f"(d[0]), "+f"(d[1]), "+f"(d[2]), "+f"(d[3])
        : "r"(a[0]), "r"(a[1]), "r"(a[2]), "r"(a[3]), "r"(b[0]), "r"(b[1]));
}
__device__ __forceinline__ void split2(float v, __half& h, __half& l) {
    h = __float2half(v);
    l = __float2half(v - __half2float(h));
}

// ---------------------------------------------------------------------------
// HMMA GEMM: C[M,N] (+)= (Ah+Al)[M,K] * B^T (+bias)(relu), B stored [N,K] fp16.
// A is 2-term fp16 (hi/lo), B single fp16 -> 2 MMAs per k16.
// CTA 128(M)x256(N), 8 warps as 2(m)x4(n) -> 64x64 warp tiles.
// K-chunk 32, 4-stage cp.async pipeline, one __syncthreads per chunk.
// grid.x = M-block (fast), grid.y = N-block (slow) -> weight L2 reuse.
// ---------------------------------------------------------------------------
#define STAGES  4
#define KC      32
#define PITCH   80u                    // 64B data + 16B pad per 32-fp16 row
#define A_TILE  (128u * PITCH)         // 10240
#define B_TILE  (256u * PITCH)         // 20480
#define STAGE_B (2u*A_TILE + B_TILE)   // 40960: Ah | Al | Bh
#define SMEM_B  (STAGES * STAGE_B)     // 163840

template<bool BIAS, bool RELU, bool ACCUM, bool SPLIT>
__global__ __launch_bounds__(256, 1)
void gemm_mma(const __half* __restrict__ Ah, const __half* __restrict__ Al,
              const __half* __restrict__ Bh,
              const float* __restrict__ bias,
              float* __restrict__ C,
              __half* __restrict__ Ch, __half* __restrict__ Cl,
              int M, int N, int K)
{
    extern __shared__ char smem_raw[];
    const uint32_t sb = smem_u32(smem_raw);

    const int tid  = threadIdx.x;
    const int wid  = tid >> 5;
    const int lane = tid & 31;
    const int row0 = blockIdx.x * 128;     // M fast
    const int col0 = blockIdx.y * 256;     // N slow
    const int NC   = K / KC;

    // stage loader: A 1024 cp16 (4/thread), B 1024 cp16 (4/thread)
    auto load_stage = [&](int s) {
        const uint32_t stg = sb + (uint32_t)(s % STAGES) * STAGE_B;
        const int k0 = s * KC;
        #pragma unroll
        for (int i = 0; i < 4; i++) {
            int f = i * 256 + tid;              // 0..1023
            int sub = f >> 9;                   // 0:Ah 1:Al
            int rem = f & 511;
            int r = rem >> 2, c = rem & 3;
            const __half* src = ((sub == 0) ? Ah : Al)
                              + (size_t)(row0 + r) * K + k0 + c * 8;
            cp16(stg + (uint32_t)sub * A_TILE + (uint32_t)r * PITCH + c * 16, src);
        }
        #pragma unroll
        for (int i = 0; i < 4; i++) {
            int f = i * 256 + tid;              // 0..1023
            int r = f >> 2, c = f & 3;
            const __half* src = Bh + (size_t)(col0 + r) * K + k0 + c * 8;
            cp16(stg + 2u*A_TILE + (uint32_t)r * PITCH + c * 16, src);
        }
        CP_COMMIT();
    };

    load_stage(0);
    if (NC > 1) load_stage(1);
    if (NC > 2) load_stage(2);

    const int wm = wid >> 2;   // 0..1 -> 64-row block
    const int wn = wid & 3;    // 0..3 -> 64-col block

    float acc[4][8][4];
    #pragma unroll
    for (int a = 0; a < 4; a++)
        #pragma unroll
        for (int b = 0; b < 8; b++)
            #pragma unroll
            for (int c = 0; c < 4; c++) acc[a][b][c] = 0.f;

    for (int i = 0; i < NC; i++) {
        int rem = NC - 1 - i;
        if (rem >= 2) CP_WAIT2(); else if (rem == 1) CP_WAIT1(); else CP_WAIT0();
        __syncthreads();
        if (i + 3 < NC) load_stage(i + 3);   // overwrites chunk i-1's stage (done)

        const uint32_t stg  = sb + (uint32_t)(i % STAGES) * STAGE_B;
        const uint32_t ah_b = stg;
        const uint32_t al_b = stg + A_TILE;
        const uint32_t bh_b = stg + 2u*A_TILE;

        #pragma unroll
        for (int ks = 0; ks < 2; ks++) {
            uint32_t ah[4][4], al[4][4], bf[8][2];
            const uint32_t a_coff = (uint32_t)ks * 32 + ((lane >> 4) << 4);
            #pragma unroll
            for (int mi = 0; mi < 4; mi++) {
                uint32_t r = (uint32_t)(wm * 64 + mi * 16 + (lane & 15));
                ldsm4(ah[mi][0], ah[mi][1], ah[mi][2], ah[mi][3], ah_b + r * PITCH + a_coff);
                ldsm4(al[mi][0], al[mi][1], al[mi][2], al[mi][3], al_b + r * PITCH + a_coff);
            }
            const uint32_t b_coff = (uint32_t)ks * 32 + (((lane >> 3) & 1) << 4);
            #pragma unroll
            for (int g = 0; g < 4; g++) {
                uint32_t r = (uint32_t)(wn * 64 + g * 16 + (lane & 7) + ((lane >> 4) << 3));
                ldsm4(bf[2*g][0], bf[2*g][1], bf[2*g+1][0], bf[2*g+1][1], bh_b + r * PITCH + b_coff);
            }
            #pragma unroll
            for (int mi = 0; mi < 4; mi++)
                #pragma unroll
                for (int ni = 0; ni < 8; ni++) {
                    mma16816(acc[mi][ni], ah[mi], bf[ni]);
                    mma16816(acc[mi][ni], al[mi], bf[ni]);
                }
        }
    }

    // ---- epilogue ----
    #pragma unroll
    for (int mi = 0; mi < 4; mi++) {
        #pragma unroll
        for (int rg = 0; rg < 2; rg++) {
            int r = row0 + wm * 64 + mi * 16 + (lane >> 2) + rg * 8;
            #pragma unroll
            for (int ni = 0; ni < 8; ni++) {
                int c = col0 + wn * 64 + ni * 8 + (lane & 3) * 2;
                float v0 = acc[mi][ni][rg * 2 + 0];
                float v1 = acc[mi][ni][rg * 2 + 1];
                if (BIAS)  { v0 += bias[c]; v1 += bias[c + 1]; }
                if (RELU)  { v0 = fmaxf(v0, 0.f); v1 = fmaxf(v1, 0.f); }
                if (ACCUM) {
                    float2 o = *(const float2*)&C[(size_t)r * N + c];
                    v0 += o.x; v1 += o.y;
                }
                if (SPLIT) {
                    __half h0, l0, h1, l1;
                    split2(v0, h0, l0); split2(v1, h1, l1);
                    *(__half2*)&Ch[(size_t)r * N + c] = __halves2half2(h0, h1);
                    *(__half2*)&Cl[(size_t)r * N + c] = __halves2half2(l0, l1);
                } else {
                    *(float2*)&C[(size_t)r * N + c] = make_float2(v0, v1);
                }
            }
        }
    }
}

// ---------------------------------------------------------------------------
// Embedding + positional encoding
// ---------------------------------------------------------------------------
__global__ void embed_kernel(const int* __restrict__ tokens,
                             const float* __restrict__ emb,
                             float* __restrict__ x)
{
    int idx = blockIdx.x * blockDim.x + threadIdx.x;
    if (idx >= MM * DD) return;
    int d  = idx & (DD - 1);
    int mt = idx >> 10;
    int b  = mt >> 11;
    int t  = mt & (TT - 1);
    int tok = (t == 0) ? 0 : tokens[b * TT + t - 1];
    int k = d & 1;
    double e = (double)(d - k) / (double)DD;
    float freq = (float)exp(-e * 11.512925464970229);   // LEN_MAX^-e
    float arg = (float)t * freq + 1.5707963267948966f * (float)k;
    x[idx] = emb[(size_t)tok * DD + d] + sinf(arg);
}

// ---------------------------------------------------------------------------
// LayerNorm -> split fp16 hi/lo output
// ---------------------------------------------------------------------------
__global__ __launch_bounds__(256) void ln_split_kernel(const float* __restrict__ x,
                                                       __half* __restrict__ yh,
                                                       __half* __restrict__ yl,
                                                       const float* __restrict__ w,
                                                       const float* __restrict__ b)
{
    __shared__ float red[8];
    int row = blockIdx.x;
    int tid = threadIdx.x;
    const float* xr = x + (size_t)row * DD;
    float4 xv = *(const float4*)&xr[tid * 4];

    float s = xv.x + xv.y + xv.z + xv.w;
    #pragma unroll
    for (int o = 16; o > 0; o >>= 1) s += __shfl_xor_sync(0xffffffffu, s, o);
    if ((tid & 31) == 0) red[tid >> 5] = s;
    __syncthreads();
    float tot = 0.f;
    #pragma unroll
    for (int i = 0; i < 8; i++) tot += red[i];
    float mean = tot * (1.0f / DD);
    __syncthreads();

    float dx0 = xv.x - mean, dx1 = xv.y - mean, dx2 = xv.z - mean, dx3 = xv.w - mean;
    float s2 = dx0*dx0 + dx1*dx1 + dx2*dx2 + dx3*dx3;
    #pragma unroll
    for (int o = 16; o > 0; o >>= 1) s2 += __shfl_xor_sync(0xffffffffu, s2, o);
    if ((tid & 31) == 0) red[tid >> 5] = s2;
    __syncthreads();
    float tot2 = 0.f;
    #pragma unroll
    for (int i = 0; i < 8; i++) tot2 += red[i];
    float inv = rsqrtf(tot2 * (1.0f / DD) + 1e-5f);

    int c = tid * 4;
    float4 wv = *(const float4*)&w[c];
    float4 bv = *(const float4*)&b[c];
    float o0 = dx0 * inv * wv.x + bv.x;
    float o1 = dx1 * inv * wv.y + bv.y;
    float o2 = dx2 * inv * wv.z + bv.z;
    float o3 = dx3 * inv * wv.w + bv.w;
    __half h0, l0, h1, l1, h2, l2, h3, l3;
    split2(o0, h0, l0); split2(o1, h1, l1); split2(o2, h2, l2); split2(o3, h3, l3);
    size_t off = (size_t)row * DD + c;
    *(__half2*)&yh[off]     = __halves2half2(h0, h1);
    *(__half2*)&yh[off + 2] = __halves2half2(h2, h3);
    *(__half2*)&yl[off]     = __halves2half2(l0, l1);
    *(__half2*)&yl[off + 2] = __halves2half2(l2, l3);
}

// ---------------------------------------------------------------------------
// Causal attention over packed qkv [M, 3072], outputs split fp16 y.
// ---------------------------------------------------------------------------
__global__ __launch_bounds__(64) void attn_kernel(const float* __restrict__ QKV,
                                                  __half* __restrict__ Yh,
                                                  __half* __restrict__ Yl)
{
    __shared__ float Ks[64][64];
    __shared__ float S[64][65];

    const int bh = blockIdx.y;
    const int b  = bh / HH;
    const int h  = bh % HH;
    const int qt = blockIdx.x;
    const int tid = threadIdx.x;
    const int t = qt * 64 + tid;
    const float scale = 0.125f;

    float q[64];
    const float* qp = QKV + (size_t)(b * TT + t) * QKVD + h * 64;
    #pragma unroll
    for (int i = 0; i < 64; i += 4) {
        float4 v4 = *(const float4*)&qp[i];
        q[i] = v4.x; q[i+1] = v4.y; q[i+2] = v4.z; q[i+3] = v4.w;
    }

    float m = -1e30f, l = 0.f;
    float acc[64];
    #pragma unroll
    for (int i = 0; i < 64; i++) acc[i] = 0.f;

    for (int s0 = 0; s0 <= qt * 64; s0 += 64) {
        __syncthreads();
        #pragma unroll
        for (int it = 0; it < 16; it++) {
            int f = it * 64 + tid;
            int r = f >> 4, c4 = (f & 15) << 2;
            *(float4*)&Ks[r][c4] =
                *(const float4*)&QKV[(size_t)(b * TT + s0 + r) * QKVD + DD + h * 64 + c4];
        }
        __syncthreads();

        float mx = -1e30f;
        for (int s = 0; s < 64; s++) {
            float d0 = 0.f, d1 = 0.f, d2 = 0.f, d3 = 0.f;
            #pragma unroll
            for (int i = 0; i < 64; i += 16) {
                float4 k0 = *(const float4*)&Ks[s][i];
                float4 k1 = *(const float4*)&Ks[s][i + 4];
                float4 k2 = *(const float4*)&Ks[s][i + 8];
                float4 k3 = *(const float4*)&Ks[s][i + 12];
                d0 += q[i+0]*k0.x + q[i+1]*k0.y + q[i+2]*k0.z + q[i+3]*k0.w;
                d1 += q[i+4]*k1.x + q[i+5]*k1.y + q[i+6]*k1.z + q[i+7]*k1.w;
                d2 += q[i+8]*k2.x + q[i+9]*k2.y + q[i+10]*k2.z + q[i+11]*k2.w;
                d3 += q[i+12]*k3.x + q[i+13]*k3.y + q[i+14]*k3.z + q[i+15]*k3.w;
            }
            float dsc = ((d0 + d1) + (d2 + d3)) * scale;
            if (s0 + s > t) dsc = -1e30f;
            S[tid][s] = dsc;
            mx = fmaxf(mx, dsc);
        }

        float mnew = fmaxf(m, mx);
        float corr = __expf(m - mnew);
        l *= corr;
        #pragma unroll
        for (int i = 0; i < 64; i++) acc[i] *= corr;
        float lsum = 0.f;
        for (int s = 0; s < 64; s++) {
            float p = __expf(S[tid][s] - mnew);
            S[tid][s] = p;
            lsum += p;
        }
        l += lsum;
        m = mnew;

        __syncthreads();
        #pragma unroll
        for (int it = 0; it < 16; it++) {
            int f = it * 64 + tid;
            int r = f >> 4, c4 = (f & 15) << 2;
            *(float4*)&Ks[r][c4] =
                *(const float4*)&QKV[(size_t)(b * TT + s0 + r) * QKVD + 2 * DD + h * 64 + c4];
        }
        __syncthreads();

        for (int s = 0; s < 64; s++) {
            float p = S[tid][s];
            #pragma unroll
            for (int i = 0; i < 64; i += 4) {
                float4 vv = *(const float4*)&Ks[s][i];
                acc[i+0] += p * vv.x;
                acc[i+1] += p * vv.y;
                acc[i+2] += p * vv.z;
                acc[i+3] += p * vv.w;
            }
        }
    }

    float inv = 1.0f / l;
    size_t yoff = (size_t)(b * TT + t) * DD + h * 64;
    #pragma unroll
    for (int i = 0; i < 64; i += 2) {
        __half h0, l0, h1, l1;
        split2(acc[i] * inv, h0, l0);
        split2(acc[i+1] * inv, h1, l1);
        *(__half2*)&Yh[yoff + i] = __halves2half2(h0, h1);
        *(__half2*)&Yl[yoff + i] = __halves2half2(l0, l1);
    }
}

// ---------------------------------------------------------------------------
// Weight conversion kernels (single fp16, vectorized x4)
// ---------------------------------------------------------------------------
__global__ void conv_kernel(const float* __restrict__ s,
                            __half* __restrict__ h, int n4)
{
    int i = blockIdx.x * blockDim.x + threadIdx.x;
    if (i >= n4) return;
    float4 v = *(const float4*)&s[i * 4];
    *(__half2*)&h[i*4]   = __halves2half2(__float2half(v.x), __float2half(v.y));
    *(__half2*)&h[i*4+2] = __halves2half2(__float2half(v.z), __float2half(v.w));
}

__global__ void pack_qkv_kernel(const float* __restrict__ wq,
                                const float* __restrict__ wk,
                                const float* __restrict__ wv,
                                __half* __restrict__ h)
{
    int i = blockIdx.x * blockDim.x + threadIdx.x;   // x4 elements
    const int per_layer4 = QKVD * DD / 4;
    if (i >= LL * per_layer4) return;
    int lyr = i / per_layer4;
    int rem = i - lyr * per_layer4;
    int row = rem >> 8;                      // 0..3071
    int c4  = rem & 255;
    int which = row >> 10;
    int srow  = row & 1023;
    const float* src = (which == 0) ? wq : ((which == 1) ? wk : wv);
    float4 v = *(const float4*)&src[(size_t)lyr * (DD*DD) + (size_t)srow * DD + c4 * 4];
    size_t o = (size_t)i * 4;
    *(__half2*)&h[o]   = __halves2half2(__float2half(v.x), __float2half(v.y));
    *(__half2*)&h[o+2] = __halves2half2(__float2half(v.z), __float2half(v.w));
}

__global__ void transpose_wo_kernel(const float* __restrict__ wo,
                                    __half* __restrict__ h)
{
    int i = blockIdx.x * blockDim.x + threadIdx.x;
    if (i >= LL * DD * DD) return;
    int lyr = i >> 20;
    int rem = i & ((1 << 20) - 1);
    int nrow = rem >> 10;
    int kcol = rem & 1023;
    h[i] = __float2half(wo[((size_t)lyr << 20) + ((size_t)kcol << 10) + nrow]);
}

// ---------------------------------------------------------------------------
// Launch
// ---------------------------------------------------------------------------
extern "C" void kernel_launch(void* const* d_in, const int* in_sizes, int n_in,
                              void* d_out, int out_size)
{
    const int*   tokens = (const int*)  d_in[0];
    const float* emb    = (const float*)d_in[1];
    const float* ln1_w  = (const float*)d_in[2];
    const float* ln1_b  = (const float*)d_in[3];
    const float* w_q    = (const float*)d_in[4];
    const float* w_k    = (const float*)d_in[5];
    const float* w_v    = (const float*)d_in[6];
    const float* w_o    = (const float*)d_in[7];
    const float* ln2_w  = (const float*)d_in[8];
    const float* ln2_b  = (const float*)d_in[9];
    const float* w1     = (const float*)d_in[10];
    const float* b1     = (const float*)d_in[11];
    const float* w2     = (const float*)d_in[12];
    const float* b2     = (const float*)d_in[13];
    const float* ro_w   = (const float*)d_in[14];
    const float* ro_b   = (const float*)d_in[15];
    float* out = (float*)d_out;

    float *x, *qkv;
    __half *xnh, *xnl, *yh, *yl, *hh, *hl, *xh, *xl;
    __half *wqkv, *wo, *w1w, *w2w, *ro;
    cudaGetSymbolAddress((void**)&x,    g_x);
    cudaGetSymbolAddress((void**)&qkv,  g_qkv);
    cudaGetSymbolAddress((void**)&xnh,  g_xnh);  cudaGetSymbolAddress((void**)&xnl, g_xnl);
    cudaGetSymbolAddress((void**)&yh,   g_yh);   cudaGetSymbolAddress((void**)&yl,  g_yl);
    cudaGetSymbolAddress((void**)&hh,   g_hh);   cudaGetSymbolAddress((void**)&hl,  g_hl);
    cudaGetSymbolAddress((void**)&xh,   g_xh);   cudaGetSymbolAddress((void**)&xl,  g_xl);
    cudaGetSymbolAddress((void**)&wqkv, g_wqkv);
    cudaGetSymbolAddress((void**)&wo,   g_wo);
    cudaGetSymbolAddress((void**)&w1w,  g_w1);
    cudaGetSymbolAddress((void**)&w2w,  g_w2);
    cudaGetSymbolAddress((void**)&ro,   g_ro);

    cudaFuncSetAttribute((const void*)gemm_mma<false,false,false,false>,
                         cudaFuncAttributeMaxDynamicSharedMemorySize, SMEM_B);
    cudaFuncSetAttribute((const void*)gemm_mma<false,false,true,false>,
                         cudaFuncAttributeMaxDynamicSharedMemorySize, SMEM_B);
    cudaFuncSetAttribute((const void*)gemm_mma<true,true,false,true>,
                         cudaFuncAttributeMaxDynamicSharedMemorySize, SMEM_B);
    cudaFuncSetAttribute((const void*)gemm_mma<true,false,true,false>,
                         cudaFuncAttributeMaxDynamicSharedMemorySize, SMEM_B);
    cudaFuncSetAttribute((const void*)gemm_mma<true,false,true,true>,
                         cudaFuncAttributeMaxDynamicSharedMemorySize, SMEM_B);
    cudaFuncSetAttribute((const void*)gemm_mma<true,false,false,false>,
                         cudaFuncAttributeMaxDynamicSharedMemorySize, SMEM_B);

    // weight conversion (every launch — weights are inputs)
    pack_qkv_kernel<<<(LL*QKVD*DD/4 + 255)/256, 256>>>(w_q, w_k, w_v, wqkv);
    transpose_wo_kernel<<<(LL*DD*DD + 255)/256, 256>>>(w_o, wo);
    conv_kernel<<<(LL*HDIM*DD/4 + 255)/256, 256>>>(w1, w1w, LL*HDIM*DD/4);
    conv_kernel<<<(LL*DD*HDIM/4 + 255)/256, 256>>>(w2, w2w, LL*DD*HDIM/4);
    conv_kernel<<<(VV*DD/4 + 255)/256, 256>>>(ro_w, ro, VV*DD/4);

    embed_kernel<<<(MM*DD + 255)/256, 256>>>(tokens, emb, x);

    // grid: x = M-block (fast), y = N-block (slow)
    const dim3 gQKV(MM/128, QKVD/256);    // 32 x 12
    const dim3 gD  (MM/128, DD/256);      // 32 x 4
    const dim3 gH  (MM/128, HDIM/256);    // 32 x 16
    const dim3 gV  (MM/128, VV/256);      // 32 x 125
    const dim3 gA  (TT/64, BB*HH);

    for (int l = 0; l < LL; l++) {
        const __half* wqkv_l = wqkv + (size_t)l * QKVD * DD;
        const __half* wo_l   = wo   + (size_t)l * DD * DD;
        const __half* w1_l   = w1w  + (size_t)l * HDIM * DD;
        const __half* w2_l   = w2w  + (size_t)l * DD * HDIM;

        ln_split_kernel<<<MM, 256>>>(x, xnh, xnl, ln1_w + (size_t)l*DD, ln1_b + (size_t)l*DD);

        gemm_mma<false,false,false,false><<<gQKV, 256, SMEM_B>>>(
            xnh, xnl, wqkv_l, nullptr, qkv, nullptr, nullptr, MM, QKVD, DD);

        attn_kernel<<<gA, 64>>>(qkv, yh, yl);

        gemm_mma<false,false,true,false><<<gD, 256, SMEM_B>>>(
            yh, yl, wo_l, nullptr, x, nullptr, nullptr, MM, DD, DD);

        ln_split_kernel<<<MM, 256>>>(x, xnh, xnl, ln2_w + (size_t)l*DD, ln2_b + (size_t)l*DD);

        gemm_mma<true,true,false,true><<<gH, 256, SMEM_B>>>(
            xnh, xnl, w1_l, b1 + (size_t)l*HDIM, nullptr, hh, hl, MM, HDIM, DD);

        if (l < LL - 1) {
            gemm_mma<true,false,true,false><<<gD, 256, SMEM_B>>>(
                hh, hl, w2_l, b2 + (size_t)l*DD, x, nullptr, nullptr, MM, DD, HDIM);
        } else {
            // last layer: fuse readout-input split into the accumulate epilogue
            gemm_mma<true,false,true,true><<<gD, 256, SMEM_B>>>(
                hh, hl, w2_l, b2 + (size_t)l*DD, x, xh, xl, MM, DD, HDIM);
        }
    }

    // readout: out = x @ ro_w^T + ro_b
    gemm_mma<true,false,false,false><<<gV, 256, SMEM_B>>>(
        xh, xl, ro, ro_b, out, nullptr, nullptr, MM, VV, DD);
}

// round 6
// speedup vs baseline: 2.6993x; 1.0478x over previous
#include <cuda_runtime.h>
#include <cuda_fp16.h>
#include <math.h>
#include <stdint.h>

// ---------------------------------------------------------------------------
// Problem constants
// ---------------------------------------------------------------------------
#define BB   2
#define TT   2048
#define DD   1024
#define HH   16
#define HDIM 4096
#define VV   32000
#define LL   4
#define MM   (BB*TT)      // 4096 rows
#define QKVD (3*DD)       // 3072

// ---------------------------------------------------------------------------
// Static device scratch (no allocations allowed)
// ---------------------------------------------------------------------------
__device__ float g_x  [MM*DD];
__device__ float g_qkv[MM*QKVD];
__device__ __half g_xnh[MM*DD],  g_xnl[MM*DD];
__device__ __half g_yh [MM*DD],  g_yl [MM*DD];
__device__ __half g_hh [MM*HDIM], g_hl [MM*HDIM];
__device__ __half g_xh [MM*DD],  g_xl [MM*DD];
// single-term fp16 weights (recomputed every launch — weights are inputs)
__device__ __half g_wqkv[LL*QKVD*DD];
__device__ __half g_wo  [LL*DD*DD];
__device__ __half g_w1  [LL*HDIM*DD];
__device__ __half g_w2  [LL*DD*HDIM];
__device__ __half g_ro  [VV*DD];

// ---------------------------------------------------------------------------
// helpers (base-target PTX only: cp.async, ldmatrix, mma.sync)
// ---------------------------------------------------------------------------
__device__ __forceinline__ uint32_t smem_u32(const void* p) {
    uint32_t a;
    asm("{ .reg .u64 t; cvta.to.shared.u64 t, %1; cvt.u32.u64 %0, t; }"
        : "=r"(a) : "l"(p));
    return a;
}
__device__ __forceinline__ void cp16(uint32_t dst, const void* src) {
    asm volatile("cp.async.cg.shared.global [%0], [%1], 16;" :: "r"(dst), "l"(src));
}
#define CP_COMMIT()  asm volatile("cp.async.commit_group;" ::: "memory")
#define CP_WAIT0()   asm volatile("cp.async.wait_group 0;" ::: "memory")
#define CP_WAIT1()   asm volatile("cp.async.wait_group 1;" ::: "memory")

__device__ __forceinline__ void ldsm4(uint32_t& r0, uint32_t& r1,
                                      uint32_t& r2, uint32_t& r3, uint32_t addr) {
    asm volatile("ldmatrix.sync.aligned.m8n8.x4.shared.b16 {%0,%1,%2,%3}, [%4];"
                 : "=r"(r0), "=r"(r1), "=r"(r2), "=r"(r3) : "r"(addr));
}
__device__ __forceinline__ void mma16816(float* d, const uint32_t* a, const uint32_t* b) {
    asm volatile("mma.sync.aligned.m16n8k16.row.col.f32.f16.f16.f32 "
        "{%0,%1,%2,%3}, {%4,%5,%6,%7}, {%8,%9}, {%0,%1,%2,%3};"
        : "+f"(d[0]), "+f"(d[1]), "+f"(d[2]), "+f"(d[3])
        : "r"(a[0]), "r"(a[1]), "r"(a[2]), "r"(a[3]), "r"(b[0]), "r"(b[1]));
}
__device__ __forceinline__ void split2(float v, __half& h, __half& l) {
    h = __float2half(v);
    l = __float2half(v - __half2float(h));
}

// ---------------------------------------------------------------------------
// HMMA GEMM: C[M,N] (+)= (Ah+Al)[M,K] * B^T (+bias)(relu), B stored [N,K] fp16.
// A is 2-term fp16 (hi/lo), B single fp16 -> 2 MMAs per k16.
// CTA 128(M)x256(N), 8 warps as 2(m)x4(n) -> 64x64 warp tiles.
// K-chunk 64, 3-stage cp.async pipeline (216KB smem), one barrier per chunk.
// grid.x = M-block (fast), grid.y = N-block (slow) -> weight L2 reuse.
// ---------------------------------------------------------------------------
#define STAGES  3
#define KC      64
#define PITCH   144u                   // 128B data + 16B pad per 64-fp16 row
#define A_TILE  (128u * PITCH)         // 18432
#define B_TILE  (256u * PITCH)         // 36864
#define STAGE_B (2u*A_TILE + B_TILE)   // 73728: Ah | Al | Bh
#define SMEM_B  (STAGES * STAGE_B)     // 221184

template<bool BIAS, bool RELU, bool ACCUM, bool SPLIT>
__global__ __launch_bounds__(256, 1)
void gemm_mma(const __half* __restrict__ Ah, const __half* __restrict__ Al,
              const __half* __restrict__ Bh,
              const float* __restrict__ bias,
              float* __restrict__ C,
              __half* __restrict__ Ch, __half* __restrict__ Cl,
              int M, int N, int K)
{
    extern __shared__ char smem_raw[];
    const uint32_t sb = smem_u32(smem_raw);

    const int tid  = threadIdx.x;
    const int wid  = tid >> 5;
    const int lane = tid & 31;
    const int row0 = blockIdx.x * 128;     // M fast
    const int col0 = blockIdx.y * 256;     // N slow
    const int NC   = K / KC;

    // stage loader: A 2048 cp16 (8/thread), B 2048 cp16 (8/thread)
    auto load_stage = [&](int s) {
        const uint32_t stg = sb + (uint32_t)(s % STAGES) * STAGE_B;
        const int k0 = s * KC;
        #pragma unroll
        for (int i = 0; i < 8; i++) {
            int f = i * 256 + tid;              // 0..2047
            int sub = f >> 10;                  // 0:Ah 1:Al
            int rem = f & 1023;
            int r = rem >> 3, c = rem & 7;
            const __half* src = ((sub == 0) ? Ah : Al)
                              + (size_t)(row0 + r) * K + k0 + c * 8;
            cp16(stg + (uint32_t)sub * A_TILE + (uint32_t)r * PITCH + c * 16, src);
        }
        #pragma unroll
        for (int i = 0; i < 8; i++) {
            int f = i * 256 + tid;              // 0..2047
            int r = f >> 3, c = f & 7;
            const __half* src = Bh + (size_t)(col0 + r) * K + k0 + c * 8;
            cp16(stg + 2u*A_TILE + (uint32_t)r * PITCH + c * 16, src);
        }
        CP_COMMIT();
    };

    load_stage(0);
    if (NC > 1) load_stage(1);

    const int wm = wid >> 2;   // 0..1 -> 64-row block
    const int wn = wid & 3;    // 0..3 -> 64-col block

    float acc[4][8][4];
    #pragma unroll
    for (int a = 0; a < 4; a++)
        #pragma unroll
        for (int b = 0; b < 8; b++)
            #pragma unroll
            for (int c = 0; c < 4; c++) acc[a][b][c] = 0.f;

    for (int i = 0; i < NC; i++) {
        if (i < NC - 1) CP_WAIT1(); else CP_WAIT0();
        __syncthreads();
        if (i + 2 < NC) load_stage(i + 2);   // buffer (i-1)%3 — compute done

        const uint32_t stg  = sb + (uint32_t)(i % STAGES) * STAGE_B;
        const uint32_t ah_b = stg;
        const uint32_t al_b = stg + A_TILE;
        const uint32_t bh_b = stg + 2u*A_TILE;

        #pragma unroll
        for (int ks = 0; ks < 4; ks++) {
            uint32_t ah[4][4], al[4][4], bf[8][2];
            const uint32_t a_coff = (uint32_t)ks * 32 + ((lane >> 4) << 4);
            #pragma unroll
            for (int mi = 0; mi < 4; mi++) {
                uint32_t r = (uint32_t)(wm * 64 + mi * 16 + (lane & 15));
                ldsm4(ah[mi][0], ah[mi][1], ah[mi][2], ah[mi][3], ah_b + r * PITCH + a_coff);
                ldsm4(al[mi][0], al[mi][1], al[mi][2], al[mi][3], al_b + r * PITCH + a_coff);
            }
            const uint32_t b_coff = (uint32_t)ks * 32 + (((lane >> 3) & 1) << 4);
            #pragma unroll
            for (int g = 0; g < 4; g++) {
                uint32_t r = (uint32_t)(wn * 64 + g * 16 + (lane & 7) + ((lane >> 4) << 3));
                ldsm4(bf[2*g][0], bf[2*g][1], bf[2*g+1][0], bf[2*g+1][1], bh_b + r * PITCH + b_coff);
            }
            #pragma unroll
            for (int mi = 0; mi < 4; mi++)
                #pragma unroll
                for (int ni = 0; ni < 8; ni++) {
                    mma16816(acc[mi][ni], ah[mi], bf[ni]);
                    mma16816(acc[mi][ni], al[mi], bf[ni]);
                }
        }
    }

    // ---- epilogue ----
    #pragma unroll
    for (int mi = 0; mi < 4; mi++) {
        #pragma unroll
        for (int rg = 0; rg < 2; rg++) {
            int r = row0 + wm * 64 + mi * 16 + (lane >> 2) + rg * 8;
            #pragma unroll
            for (int ni = 0; ni < 8; ni++) {
                int c = col0 + wn * 64 + ni * 8 + (lane & 3) * 2;
                float v0 = acc[mi][ni][rg * 2 + 0];
                float v1 = acc[mi][ni][rg * 2 + 1];
                if (BIAS)  { v0 += bias[c]; v1 += bias[c + 1]; }
                if (RELU)  { v0 = fmaxf(v0, 0.f); v1 = fmaxf(v1, 0.f); }
                if (ACCUM) {
                    float2 o = *(const float2*)&C[(size_t)r * N + c];
                    v0 += o.x; v1 += o.y;
                }
                if (SPLIT) {
                    __half h0, l0, h1, l1;
                    split2(v0, h0, l0); split2(v1, h1, l1);
                    *(__half2*)&Ch[(size_t)r * N + c] = __halves2half2(h0, h1);
                    *(__half2*)&Cl[(size_t)r * N + c] = __halves2half2(l0, l1);
                } else {
                    *(float2*)&C[(size_t)r * N + c] = make_float2(v0, v1);
                }
            }
        }
    }
}

// ---------------------------------------------------------------------------
// Fused embedding + positional encoding + LayerNorm(ln1, layer 0).
// One block per row: writes x (fp32 residual base) and split-fp16 ln output.
// ---------------------------------------------------------------------------
__global__ __launch_bounds__(256) void embed_ln_kernel(const int* __restrict__ tokens,
                                                       const float* __restrict__ emb,
                                                       const float* __restrict__ w,
                                                       const float* __restrict__ b,
                                                       float* __restrict__ x,
                                                       __half* __restrict__ yh,
                                                       __half* __restrict__ yl)
{
    __shared__ float red[8];
    int row = blockIdx.x;
    int tid = threadIdx.x;
    int bb  = row >> 11;
    int t   = row & (TT - 1);
    int tok = (t == 0) ? 0 : tokens[bb * TT + t - 1];

    int c = tid * 4;
    float v[4];
    #pragma unroll
    for (int j = 0; j < 4; j++) {
        int d = c + j;
        int k = d & 1;
        double e = (double)(d - k) / (double)DD;
        float freq = (float)exp(-e * 11.512925464970229);   // LEN_MAX^-e
        float arg = (float)t * freq + 1.5707963267948966f * (float)k;
        v[j] = emb[(size_t)tok * DD + d] + sinf(arg);
    }
    *(float4*)&x[(size_t)row * DD + c] = make_float4(v[0], v[1], v[2], v[3]);

    float s = v[0] + v[1] + v[2] + v[3];
    #pragma unroll
    for (int o = 16; o > 0; o >>= 1) s += __shfl_xor_sync(0xffffffffu, s, o);
    if ((tid & 31) == 0) red[tid >> 5] = s;
    __syncthreads();
    float tot = 0.f;
    #pragma unroll
    for (int i = 0; i < 8; i++) tot += red[i];
    float mean = tot * (1.0f / DD);
    __syncthreads();

    float dx0 = v[0]-mean, dx1 = v[1]-mean, dx2 = v[2]-mean, dx3 = v[3]-mean;
    float s2 = dx0*dx0 + dx1*dx1 + dx2*dx2 + dx3*dx3;
    #pragma unroll
    for (int o = 16; o > 0; o >>= 1) s2 += __shfl_xor_sync(0xffffffffu, s2, o);
    if ((tid & 31) == 0) red[tid >> 5] = s2;
    __syncthreads();
    float tot2 = 0.f;
    #pragma unroll
    for (int i = 0; i < 8; i++) tot2 += red[i];
    float inv = rsqrtf(tot2 * (1.0f / DD) + 1e-5f);

    float4 wv = *(const float4*)&w[c];
    float4 bv = *(const float4*)&b[c];
    float o0 = dx0 * inv * wv.x + bv.x;
    float o1 = dx1 * inv * wv.y + bv.y;
    float o2 = dx2 * inv * wv.z + bv.z;
    float o3 = dx3 * inv * wv.w + bv.w;
    __half h0, l0, h1, l1, h2, l2, h3, l3;
    split2(o0, h0, l0); split2(o1, h1, l1); split2(o2, h2, l2); split2(o3, h3, l3);
    size_t off = (size_t)row * DD + c;
    *(__half2*)&yh[off]     = __halves2half2(h0, h1);
    *(__half2*)&yh[off + 2] = __halves2half2(h2, h3);
    *(__half2*)&yl[off]     = __halves2half2(l0, l1);
    *(__half2*)&yl[off + 2] = __halves2half2(l2, l3);
}

// ---------------------------------------------------------------------------
// LayerNorm -> split fp16 hi/lo output
// ---------------------------------------------------------------------------
__global__ __launch_bounds__(256) void ln_split_kernel(const float* __restrict__ x,
                                                       __half* __restrict__ yh,
                                                       __half* __restrict__ yl,
                                                       const float* __restrict__ w,
                                                       const float* __restrict__ b)
{
    __shared__ float red[8];
    int row = blockIdx.x;
    int tid = threadIdx.x;
    const float* xr = x + (size_t)row * DD;
    float4 xv = *(const float4*)&xr[tid * 4];

    float s = xv.x + xv.y + xv.z + xv.w;
    #pragma unroll
    for (int o = 16; o > 0; o >>= 1) s += __shfl_xor_sync(0xffffffffu, s, o);
    if ((tid & 31) == 0) red[tid >> 5] = s;
    __syncthreads();
    float tot = 0.f;
    #pragma unroll
    for (int i = 0; i < 8; i++) tot += red[i];
    float mean = tot * (1.0f / DD);
    __syncthreads();

    float dx0 = xv.x - mean, dx1 = xv.y - mean, dx2 = xv.z - mean, dx3 = xv.w - mean;
    float s2 = dx0*dx0 + dx1*dx1 + dx2*dx2 + dx3*dx3;
    #pragma unroll
    for (int o = 16; o > 0; o >>= 1) s2 += __shfl_xor_sync(0xffffffffu, s2, o);
    if ((tid & 31) == 0) red[tid >> 5] = s2;
    __syncthreads();
    float tot2 = 0.f;
    #pragma unroll
    for (int i = 0; i < 8; i++) tot2 += red[i];
    float inv = rsqrtf(tot2 * (1.0f / DD) + 1e-5f);

    int c = tid * 4;
    float4 wv = *(const float4*)&w[c];
    float4 bv = *(const float4*)&b[c];
    float o0 = dx0 * inv * wv.x + bv.x;
    float o1 = dx1 * inv * wv.y + bv.y;
    float o2 = dx2 * inv * wv.z + bv.z;
    float o3 = dx3 * inv * wv.w + bv.w;
    __half h0, l0, h1, l1, h2, l2, h3, l3;
    split2(o0, h0, l0); split2(o1, h1, l1); split2(o2, h2, l2); split2(o3, h3, l3);
    size_t off = (size_t)row * DD + c;
    *(__half2*)&yh[off]     = __halves2half2(h0, h1);
    *(__half2*)&yh[off + 2] = __halves2half2(h2, h3);
    *(__half2*)&yl[off]     = __halves2half2(l0, l1);
    *(__half2*)&yl[off + 2] = __halves2half2(l2, l3);
}

// ---------------------------------------------------------------------------
// Causal attention over packed qkv [M, 3072], outputs split fp16 y.
// ---------------------------------------------------------------------------
__global__ __launch_bounds__(64) void attn_kernel(const float* __restrict__ QKV,
                                                  __half* __restrict__ Yh,
                                                  __half* __restrict__ Yl)
{
    __shared__ float Ks[64][64];
    __shared__ float S[64][65];

    const int bh = blockIdx.y;
    const int b  = bh / HH;
    const int h  = bh % HH;
    const int qt = blockIdx.x;
    const int tid = threadIdx.x;
    const int t = qt * 64 + tid;
    const float scale = 0.125f;

    float q[64];
    const float* qp = QKV + (size_t)(b * TT + t) * QKVD + h * 64;
    #pragma unroll
    for (int i = 0; i < 64; i += 4) {
        float4 v4 = *(const float4*)&qp[i];
        q[i] = v4.x; q[i+1] = v4.y; q[i+2] = v4.z; q[i+3] = v4.w;
    }

    float m = -1e30f, l = 0.f;
    float acc[64];
    #pragma unroll
    for (int i = 0; i < 64; i++) acc[i] = 0.f;

    for (int s0 = 0; s0 <= qt * 64; s0 += 64) {
        __syncthreads();
        #pragma unroll
        for (int it = 0; it < 16; it++) {
            int f = it * 64 + tid;
            int r = f >> 4, c4 = (f & 15) << 2;
            *(float4*)&Ks[r][c4] =
                *(const float4*)&QKV[(size_t)(b * TT + s0 + r) * QKVD + DD + h * 64 + c4];
        }
        __syncthreads();

        float mx = -1e30f;
        for (int s = 0; s < 64; s++) {
            float d0 = 0.f, d1 = 0.f, d2 = 0.f, d3 = 0.f;
            #pragma unroll
            for (int i = 0; i < 64; i += 16) {
                float4 k0 = *(const float4*)&Ks[s][i];
                float4 k1 = *(const float4*)&Ks[s][i + 4];
                float4 k2 = *(const float4*)&Ks[s][i + 8];
                float4 k3 = *(const float4*)&Ks[s][i + 12];
                d0 += q[i+0]*k0.x + q[i+1]*k0.y + q[i+2]*k0.z + q[i+3]*k0.w;
                d1 += q[i+4]*k1.x + q[i+5]*k1.y + q[i+6]*k1.z + q[i+7]*k1.w;
                d2 += q[i+8]*k2.x + q[i+9]*k2.y + q[i+10]*k2.z + q[i+11]*k2.w;
                d3 += q[i+12]*k3.x + q[i+13]*k3.y + q[i+14]*k3.z + q[i+15]*k3.w;
            }
            float dsc = ((d0 + d1) + (d2 + d3)) * scale;
            if (s0 + s > t) dsc = -1e30f;
            S[tid][s] = dsc;
            mx = fmaxf(mx, dsc);
        }

        float mnew = fmaxf(m, mx);
        float corr = __expf(m - mnew);
        l *= corr;
        #pragma unroll
        for (int i = 0; i < 64; i++) acc[i] *= corr;
        float lsum = 0.f;
        for (int s = 0; s < 64; s++) {
            float p = __expf(S[tid][s] - mnew);
            S[tid][s] = p;
            lsum += p;
        }
        l += lsum;
        m = mnew;

        __syncthreads();
        #pragma unroll
        for (int it = 0; it < 16; it++) {
            int f = it * 64 + tid;
            int r = f >> 4, c4 = (f & 15) << 2;
            *(float4*)&Ks[r][c4] =
                *(const float4*)&QKV[(size_t)(b * TT + s0 + r) * QKVD + 2 * DD + h * 64 + c4];
        }
        __syncthreads();

        for (int s = 0; s < 64; s++) {
            float p = S[tid][s];
            #pragma unroll
            for (int i = 0; i < 64; i += 4) {
                float4 vv = *(const float4*)&Ks[s][i];
                acc[i+0] += p * vv.x;
                acc[i+1] += p * vv.y;
                acc[i+2] += p * vv.z;
                acc[i+3] += p * vv.w;
            }
        }
    }

    float inv = 1.0f / l;
    size_t yoff = (size_t)(b * TT + t) * DD + h * 64;
    #pragma unroll
    for (int i = 0; i < 64; i += 2) {
        __half h0, l0, h1, l1;
        split2(acc[i] * inv, h0, l0);
        split2(acc[i+1] * inv, h1, l1);
        *(__half2*)&Yh[yoff + i] = __halves2half2(h0, h1);
        *(__half2*)&Yl[yoff + i] = __halves2half2(l0, l1);
    }
}

// ---------------------------------------------------------------------------
// Weight conversion kernels (single fp16, vectorized x4)
// ---------------------------------------------------------------------------
__global__ void conv_kernel(const float* __restrict__ s,
                            __half* __restrict__ h, int n4)
{
    int i = blockIdx.x * blockDim.x + threadIdx.x;
    if (i >= n4) return;
    float4 v = *(const float4*)&s[i * 4];
    *(__half2*)&h[i*4]   = __halves2half2(__float2half(v.x), __float2half(v.y));
    *(__half2*)&h[i*4+2] = __halves2half2(__float2half(v.z), __float2half(v.w));
}

__global__ void pack_qkv_kernel(const float* __restrict__ wq,
                                const float* __restrict__ wk,
                                const float* __restrict__ wv,
                                __half* __restrict__ h)
{
    int i = blockIdx.x * blockDim.x + threadIdx.x;   // x4 elements
    const int per_layer4 = QKVD * DD / 4;
    if (i >= LL * per_layer4) return;
    int lyr = i / per_layer4;
    int rem = i - lyr * per_layer4;
    int row = rem >> 8;                      // 0..3071
    int c4  = rem & 255;
    int which = row >> 10;
    int srow  = row & 1023;
    const float* src = (which == 0) ? wq : ((which == 1) ? wk : wv);
    float4 v = *(const float4*)&src[(size_t)lyr * (DD*DD) + (size_t)srow * DD + c4 * 4];
    size_t o = (size_t)i * 4;
    *(__half2*)&h[o]   = __halves2half2(__float2half(v.x), __float2half(v.y));
    *(__half2*)&h[o+2] = __halves2half2(__float2half(v.z), __float2half(v.w));
}

__global__ void transpose_wo_kernel(const float* __restrict__ wo,
                                    __half* __restrict__ h)
{
    int i = blockIdx.x * blockDim.x + threadIdx.x;
    if (i >= LL * DD * DD) return;
    int lyr = i >> 20;
    int rem = i & ((1 << 20) - 1);
    int nrow = rem >> 10;
    int kcol = rem & 1023;
    h[i] = __float2half(wo[((size_t)lyr << 20) + ((size_t)kcol << 10) + nrow]);
}

// ---------------------------------------------------------------------------
// Launch
// ---------------------------------------------------------------------------
extern "C" void kernel_launch(void* const* d_in, const int* in_sizes, int n_in,
                              void* d_out, int out_size)
{
    const int*   tokens = (const int*)  d_in[0];
    const float* emb    = (const float*)d_in[1];
    const float* ln1_w  = (const float*)d_in[2];
    const float* ln1_b  = (const float*)d_in[3];
    const float* w_q    = (const float*)d_in[4];
    const float* w_k    = (const float*)d_in[5];
    const float* w_v    = (const float*)d_in[6];
    const float* w_o    = (const float*)d_in[7];
    const float* ln2_w  = (const float*)d_in[8];
    const float* ln2_b  = (const float*)d_in[9];
    const float* w1     = (const float*)d_in[10];
    const float* b1     = (const float*)d_in[11];
    const float* w2     = (const float*)d_in[12];
    const float* b2     = (const float*)d_in[13];
    const float* ro_w   = (const float*)d_in[14];
    const float* ro_b   = (const float*)d_in[15];
    float* out = (float*)d_out;

    float *x, *qkv;
    __half *xnh, *xnl, *yh, *yl, *hh, *hl, *xh, *xl;
    __half *wqkv, *wo, *w1w, *w2w, *ro;
    cudaGetSymbolAddress((void**)&x,    g_x);
    cudaGetSymbolAddress((void**)&qkv,  g_qkv);
    cudaGetSymbolAddress((void**)&xnh,  g_xnh);  cudaGetSymbolAddress((void**)&xnl, g_xnl);
    cudaGetSymbolAddress((void**)&yh,   g_yh);   cudaGetSymbolAddress((void**)&yl,  g_yl);
    cudaGetSymbolAddress((void**)&hh,   g_hh);   cudaGetSymbolAddress((void**)&hl,  g_hl);
    cudaGetSymbolAddress((void**)&xh,   g_xh);   cudaGetSymbolAddress((void**)&xl,  g_xl);
    cudaGetSymbolAddress((void**)&wqkv, g_wqkv);
    cudaGetSymbolAddress((void**)&wo,   g_wo);
    cudaGetSymbolAddress((void**)&w1w,  g_w1);
    cudaGetSymbolAddress((void**)&w2w,  g_w2);
    cudaGetSymbolAddress((void**)&ro,   g_ro);

    cudaFuncSetAttribute((const void*)gemm_mma<false,false,false,false>,
                         cudaFuncAttributeMaxDynamicSharedMemorySize, SMEM_B);
    cudaFuncSetAttribute((const void*)gemm_mma<false,false,true,false>,
                         cudaFuncAttributeMaxDynamicSharedMemorySize, SMEM_B);
    cudaFuncSetAttribute((const void*)gemm_mma<true,true,false,true>,
                         cudaFuncAttributeMaxDynamicSharedMemorySize, SMEM_B);
    cudaFuncSetAttribute((const void*)gemm_mma<true,false,true,false>,
                         cudaFuncAttributeMaxDynamicSharedMemorySize, SMEM_B);
    cudaFuncSetAttribute((const void*)gemm_mma<true,false,true,true>,
                         cudaFuncAttributeMaxDynamicSharedMemorySize, SMEM_B);
    cudaFuncSetAttribute((const void*)gemm_mma<true,false,false,false>,
                         cudaFuncAttributeMaxDynamicSharedMemorySize, SMEM_B);

    // grid: x = M-block (fast), y = N-block (slow)
    const dim3 gQKV(MM/128, QKVD/256);    // 32 x 12
    const dim3 gD  (MM/128, DD/256);      // 32 x 4
    const dim3 gH  (MM/128, HDIM/256);    // 32 x 16
    const dim3 gV  (MM/128, VV/256);      // 32 x 125
    const dim3 gA  (TT/64, BB*HH);

    // Launch order places the main GEMM at index 2 / 3rd unique kernel so the
    // profiler (-s 5 -c 1 with its observed skip behavior) captures it.
    pack_qkv_kernel<<<(LL*QKVD*DD/4 + 255)/256, 256>>>(w_q, w_k, w_v, wqkv);          // 0
    embed_ln_kernel<<<MM, 256>>>(tokens, emb, ln1_w, ln1_b, x, xnh, xnl);             // 1
    gemm_mma<false,false,false,false><<<gQKV, 256, SMEM_B>>>(                          // 2
        xnh, xnl, wqkv, nullptr, qkv, nullptr, nullptr, MM, QKVD, DD);
    transpose_wo_kernel<<<(LL*DD*DD + 255)/256, 256>>>(w_o, wo);                       // 3
    conv_kernel<<<(LL*HDIM*DD/4 + 255)/256, 256>>>(w1, w1w, LL*HDIM*DD/4);            // 4
    conv_kernel<<<(LL*DD*HDIM/4 + 255)/256, 256>>>(w2, w2w, LL*DD*HDIM/4);            // 5
    conv_kernel<<<(VV*DD/4 + 255)/256, 256>>>(ro_w, ro, VV*DD/4);                     // 6

    for (int l = 0; l < LL; l++) {
        const __half* wqkv_l = wqkv + (size_t)l * QKVD * DD;
        const __half* wo_l   = wo   + (size_t)l * DD * DD;
        const __half* w1_l   = w1w  + (size_t)l * HDIM * DD;
        const __half* w2_l   = w2w  + (size_t)l * DD * HDIM;

        if (l > 0) {
            ln_split_kernel<<<MM, 256>>>(x, xnh, xnl, ln1_w + (size_t)l*DD, ln1_b + (size_t)l*DD);
            gemm_mma<false,false,false,false><<<gQKV, 256, SMEM_B>>>(
                xnh, xnl, wqkv_l, nullptr, qkv, nullptr, nullptr, MM, QKVD, DD);
        }

        attn_kernel<<<gA, 64>>>(qkv, yh, yl);

        gemm_mma<false,false,true,false><<<gD, 256, SMEM_B>>>(
            yh, yl, wo_l, nullptr, x, nullptr, nullptr, MM, DD, DD);

        ln_split_kernel<<<MM, 256>>>(x, xnh, xnl, ln2_w + (size_t)l*DD, ln2_b + (size_t)l*DD);

        gemm_mma<true,true,false,true><<<gH, 256, SMEM_B>>>(
            xnh, xnl, w1_l, b1 + (size_t)l*HDIM, nullptr, hh, hl, MM, HDIM, DD);

        if (l < LL - 1) {
            gemm_mma<true,false,true,false><<<gD, 256, SMEM_B>>>(
                hh, hl, w2_l, b2 + (size_t)l*DD, x, nullptr, nullptr, MM, DD, HDIM);
        } else {
            // last layer: fuse readout-input split into the accumulate epilogue
            gemm_mma<true,false,true,true><<<gD, 256, SMEM_B>>>(
                hh, hl, w2_l, b2 + (size_t)l*DD, x, xh, xl, MM, DD, HDIM);
        }
    }

    // readout: out = x @ ro_w^T + ro_b
    gemm_mma<true,false,false,false><<<gV, 256, SMEM_B>>>(
        xh, xl, ro, ro_b, out, nullptr, nullptr, MM, VV, DD);
}